// round 3
// baseline (speedup 1.0000x reference)
#include <cuda_runtime.h>
#include <cstdint>
#include <cstddef>

#define EPSV 1e-5f
constexpr int NND = 100000;   // nodes
constexpr int NE  = 800000;   // edges
constexpr int NP  = 100032;   // nodes padded to multiple of 64

// ---------------- scratch layout in one big device buffer ----------------
constexpr size_t OFF_AGG1 = 0;                               // NP*32   (zeroed)
constexpr size_t OFF_CNT  = OFF_AGG1 + (size_t)NP*32;        // NP      (zeroed)
constexpr size_t OFF_AGG2 = OFF_CNT  + (size_t)NP;           // NP*128  (zeroed)
constexpr size_t OFF_STAT = OFF_AGG2 + (size_t)NP*128;       // 1024    (zeroed)
constexpr size_t ZERO_FLOATS = OFF_STAT + 1024;
constexpr size_t OFF_XP   = ZERO_FLOATS;                     // NP*32
constexpr size_t OFF_M1   = OFF_XP  + (size_t)NP*32;         // NP*32
constexpr size_t OFF_H1   = OFF_M1  + (size_t)NP*32;         // NP*128
constexpr size_t OFF_M2   = OFF_H1  + (size_t)NP*128;        // NP*128
constexpr size_t OFF_H2   = OFF_M2  + (size_t)NP*128;        // NP*128
constexpr size_t OFF_UV   = OFF_H2  + (size_t)NP*128;        // NP*256
constexpr size_t OFF_RE   = OFF_UV  + (size_t)NP*256;        // NE*128
constexpr size_t OFF_Z1   = OFF_RE  + (size_t)NE*128;        // NE*128
constexpr size_t OFF_WC1  = OFF_Z1  + (size_t)NE*128;        // 64*128
constexpr size_t OFF_WC2  = OFF_WC1 + 64*128;                // 256*128
constexpr size_t OFF_BUV  = OFF_WC2 + 256*128;               // 128*256
constexpr size_t OFF_W1CF = OFF_BUV + 128*256;               // 128*128
constexpr size_t OFF_BM1F = OFF_W1CF + 128*128;              // 128
constexpr size_t OFF_W2F  = OFF_BM1F + 128;                  // 128*64
constexpr size_t OFF_B2F  = OFF_W2F + 128*64;                // 64
constexpr size_t GBUF_TOTAL = OFF_B2F + 64;

__device__ float g_buf[GBUF_TOTAL];

// stat sub-offsets (within OFF_STAT): bn1 sum/sq, bn2, bne, bnm
// +0, +128, +256, +384, +512, +640, +768, +896

// ---------------- generic register-blocked GEMM with fused epilogues ----------------
// C[M,BNtot] = A[M,K] @ B[K,BNtot]  (A optionally split into two halves along K)
// EPI 0: +bias, store
// EPI 1: +bias, store, accumulate column stats (rows < Mreal)
// EPI 2: +bias, relu, store, stats
// EPI 3: +bias, + uv[es]*u + uv[et]*v gather, relu, store, stats
// EPI 4: +bias, relu, row-dot with wv, reduce, write outv (+*wb)
template<int K, int BN, int TM, int TN, int EPI, bool SPLITA>
__global__ void __launch_bounds__(128)
gemm_k(const float* __restrict__ A0, const float* __restrict__ A1,
       const float* __restrict__ B, int ldb,
       const float* __restrict__ bias,
       float* __restrict__ C, int ldc, int Mreal,
       const int* __restrict__ es, const int* __restrict__ et,
       const float* __restrict__ uv,
       float* __restrict__ gsum, float* __restrict__ gsq,
       const float* __restrict__ wv, const float* __restrict__ wb,
       float* __restrict__ outv)
{
    constexpr int BM = 64, BK = 16;
    constexpr int TCOLS = BN / TN;
    constexpr int LDA = SPLITA ? (K/2) : K;

    __shared__ float As[BK][BM + 4];
    __shared__ float Bs[BK][BN];
    __shared__ float s_sum[(EPI>=1 && EPI<=3) ? BN : 1];
    __shared__ float s_sq [(EPI>=1 && EPI<=3) ? BN : 1];
    __shared__ float s_red[(EPI==4) ? (BM*(TCOLS+1)) : 1];

    const int tid = threadIdx.x;
    const int row0 = blockIdx.x * BM;
    const int colblk = blockIdx.y * BN;

    float acc[TM][TN];
#pragma unroll
    for (int i=0;i<TM;i++)
#pragma unroll
        for (int j=0;j<TN;j++) acc[i][j]=0.f;

    const int tc = tid % TCOLS, tr = tid / TCOLS;

    for (int k0 = 0; k0 < K; k0 += BK) {
        // A tile (BM x BK) -> transposed As[k][m]
#pragma unroll
        for (int p = 0; p < 2; ++p) {
            int ar = (tid >> 2) + p*32;
            int ac = (tid & 3) * 4;
            int grow = row0 + ar;
            int gk = k0 + ac;
            const float* Ap = A0; int kk = gk;
            if (SPLITA && gk >= K/2) { Ap = A1; kk = gk - K/2; }
            float4 v = *reinterpret_cast<const float4*>(Ap + (size_t)grow*LDA + kk);
            As[ac+0][ar]=v.x; As[ac+1][ar]=v.y; As[ac+2][ar]=v.z; As[ac+3][ar]=v.w;
        }
        // B tile (BK x BN)
        constexpr int BLD = (BK*BN)/(128*4);
#pragma unroll
        for (int p = 0; p < BLD; ++p) {
            int lin = tid + p*128;
            int br = lin / (BN/4);
            int bc = (lin % (BN/4)) * 4;
            float4 v = *reinterpret_cast<const float4*>(B + (size_t)(k0+br)*ldb + colblk + bc);
            *reinterpret_cast<float4*>(&Bs[br][bc]) = v;
        }
        __syncthreads();
#pragma unroll
        for (int kk = 0; kk < BK; ++kk) {
            float a[TM], b[TN];
#pragma unroll
            for (int i=0;i<TM;i++) a[i] = As[kk][tr*TM+i];
#pragma unroll
            for (int j=0;j<TN;j++) b[j] = Bs[kk][tc*TN+j];
#pragma unroll
            for (int i=0;i<TM;i++)
#pragma unroll
                for (int j=0;j<TN;j++) acc[i][j] = fmaf(a[i], b[j], acc[i][j]);
        }
        __syncthreads();
    }

    const int gc0 = colblk + tc*TN;
    float breg[TN];
#pragma unroll
    for (int j=0;j<TN;j++) breg[j] = bias ? bias[gc0+j] : 0.f;

    float cs[TN], cq[TN];
#pragma unroll
    for (int j=0;j<TN;j++){ cs[j]=0.f; cq[j]=0.f; }

    if constexpr (EPI == 0 || EPI == 1) {
#pragma unroll
        for (int i=0;i<TM;i++){
            int r = row0 + tr*TM + i;
#pragma unroll
            for (int j=0;j<TN;j++){
                float v = acc[i][j] + breg[j];
                C[(size_t)r*ldc + gc0 + j] = v;
                if (EPI==1 && r < Mreal){ cs[j]+=v; cq[j]+=v*v; }
            }
        }
    } else if constexpr (EPI == 2) {
#pragma unroll
        for (int i=0;i<TM;i++){
            int r = row0 + tr*TM + i;
#pragma unroll
            for (int j=0;j<TN;j++){
                float v = fmaxf(acc[i][j] + breg[j], 0.f);
                C[(size_t)r*ldc + gc0 + j] = v;
                if (r < Mreal){ cs[j]+=v; cq[j]+=v*v; }
            }
        }
    } else if constexpr (EPI == 3) {
#pragma unroll
        for (int i=0;i<TM;i++){
            int r = row0 + tr*TM + i;
            int e1 = es[r], e2 = et[r];
            const float* up = uv + (size_t)e1*256 + gc0;
            const float* vp = uv + (size_t)e2*256 + 128 + gc0;
#pragma unroll
            for (int j=0;j<TN;j++){
                float v = fmaxf(acc[i][j] + breg[j] + up[j] + vp[j], 0.f);
                C[(size_t)r*ldc + gc0 + j] = v;
                cs[j]+=v; cq[j]+=v*v;
            }
        }
    } else if constexpr (EPI == 4) {
        float wreg[TN];
#pragma unroll
        for (int j=0;j<TN;j++) wreg[j] = wv[gc0+j];
#pragma unroll
        for (int i=0;i<TM;i++){
            float p = 0.f;
#pragma unroll
            for (int j=0;j<TN;j++){
                float v = fmaxf(acc[i][j] + breg[j], 0.f);
                p = fmaf(v, wreg[j], p);
            }
            s_red[(tr*TM+i)*(TCOLS+1) + tc] = p;
        }
        __syncthreads();
        if (tid < BM){
            float s = 0.f;
#pragma unroll
            for (int t=0;t<TCOLS;t++) s += s_red[tid*(TCOLS+1)+t];
            outv[row0 + tid] = s + wb[0];
        }
    }

    if constexpr (EPI >= 1 && EPI <= 3) {
        for (int i=tid;i<BN;i+=128){ s_sum[i]=0.f; s_sq[i]=0.f; }
        __syncthreads();
#pragma unroll
        for (int j=0;j<TN;j++){
            atomicAdd(&s_sum[tc*TN+j], cs[j]);
            atomicAdd(&s_sq [tc*TN+j], cq[j]);
        }
        __syncthreads();
        for (int i=tid;i<BN;i+=128){
            atomicAdd(&gsum[colblk+i], s_sum[i]);
            atomicAdd(&gsq [colblk+i], s_sq[i]);
        }
    }
}

// ---------------- elementwise / scatter / prep kernels ----------------
__global__ void k_copy_x(const float* __restrict__ x, float* __restrict__ xp){
    int i = blockIdx.x*256 + threadIdx.x;
    if (i < NP*32) xp[i] = (i < NND*32) ? x[i] : 0.f;
}

__global__ void k_prep_weights(const float* __restrict__ W1l, const float* __restrict__ W1r,
                               const float* __restrict__ W2l, const float* __restrict__ W2r,
                               const float* __restrict__ Wm1, float* __restrict__ gb){
    int i = blockIdx.x*256 + threadIdx.x;
    if (i < 64*128){
        int r = i>>7, c = i&127;
        gb[OFF_WC1 + i] = (r<32) ? W1l[r*128+c] : W1r[(r-32)*128+c];
    } else if (i < 64*128 + 256*128){
        int j = i - 64*128; int r = j>>7, c = j&127;
        gb[OFF_WC2 + j] = (r<128) ? W2l[r*128+c] : W2r[(r-128)*128+c];
    } else if (i < 64*128 + 256*128 + 128*256){
        int j = i - 64*128 - 256*128; int k = j>>8, c = j&255;
        gb[OFF_BUV + j] = (c<128) ? Wm1[k*128+c] : Wm1[(128+k)*128 + (c-128)];
    }
}

__global__ void k_scatter1(const float* __restrict__ x, const int* __restrict__ src,
                           const int* __restrict__ dst, float* __restrict__ agg1,
                           float* __restrict__ cnt){
    int idx = blockIdx.x*256 + threadIdx.x;
    if (idx >= NE*8) return;
    int e = idx >> 3, q = idx & 7;
    int s = src[e], d = dst[e];
    float4 v = *reinterpret_cast<const float4*>(x + (size_t)s*32 + q*4);
    float* p = agg1 + (size_t)d*32 + q*4;
    atomicAdd(p+0, v.x); atomicAdd(p+1, v.y); atomicAdd(p+2, v.z); atomicAdd(p+3, v.w);
    if (q == 0) atomicAdd(cnt + d, 1.f);
}

__global__ void k_scatter2(const float* __restrict__ h1, const int* __restrict__ src,
                           const int* __restrict__ dst, float* __restrict__ agg2){
    int idx = blockIdx.x*256 + threadIdx.x;
    if (idx >= NE*32) return;
    int e = idx >> 5, q = idx & 31;
    int s = src[e], d = dst[e];
    float4 v = *reinterpret_cast<const float4*>(h1 + (size_t)s*128 + q*4);
    float* p = agg2 + (size_t)d*128 + q*4;
    atomicAdd(p+0, v.x); atomicAdd(p+1, v.y); atomicAdd(p+2, v.z); atomicAdd(p+3, v.w);
}

__global__ void k_mean(float* __restrict__ mean, const float* __restrict__ agg,
                       const float* __restrict__ cnt, int total, int F){
    int i = blockIdx.x*256 + threadIdx.x;
    if (i >= total) return;
    mean[i] = agg[i] / fmaxf(cnt[i/F], 1.f);
}

__global__ void k_bnapply(float* __restrict__ buf, int n,
                          const float* __restrict__ ss, const float* __restrict__ sq,
                          const float* __restrict__ g, const float* __restrict__ b){
    int i = blockIdx.x*256 + threadIdx.x;
    if (i >= n*128) return;
    int c = i & 127;
    float m = ss[c] / (float)n;
    float var = sq[c] / (float)n - m*m;
    float s = g[c] * rsqrtf(var + EPSV);
    float v = buf[i]*s + (b[c] - m*s);
    buf[i] = fmaxf(v, 0.f);
}

// fold ef-BN (stats over RE) into Wm1_C and bias
__global__ void k_prep_ef(const float* __restrict__ Wm1, const float* __restrict__ bm1,
                          const float* __restrict__ bg, const float* __restrict__ bb,
                          float* __restrict__ gb){
    __shared__ float se[128], te[128];
    int t = threadIdx.x;
    float m = gb[OFF_STAT + 512 + t] / (float)NE;
    float var = gb[OFF_STAT + 640 + t] / (float)NE - m*m;
    float s = bg[t] * rsqrtf(var + EPSV);
    se[t] = s; te[t] = bb[t] - m*s;
    __syncthreads();
    float bacc = bm1[t];
    for (int k = 0; k < 128; ++k){
        float w = Wm1[(size_t)(256+k)*128 + t];
        gb[OFF_W1CF + k*128 + t] = se[k]*w;
        bacc += te[k]*w;
    }
    gb[OFF_BM1F + t] = bacc;
}

// fold bnm (stats over z1) into Wm2 and bias
__global__ void k_prep_m(const float* __restrict__ Wm2, const float* __restrict__ bm2,
                         const float* __restrict__ bg, const float* __restrict__ bb,
                         float* __restrict__ gb){
    __shared__ float sm[128], tm[128];
    int t = threadIdx.x;
    float m = gb[OFF_STAT + 768 + t] / (float)NE;
    float var = gb[OFF_STAT + 896 + t] / (float)NE - m*m;
    float s = bg[t] * rsqrtf(var + EPSV);
    sm[t] = s; tm[t] = bb[t] - m*s;
    __syncthreads();
    if (t < 64){
        float b = bm2[t];
        for (int k = 0; k < 128; ++k){
            float w = Wm2[k*64 + t];
            gb[OFF_W2F + k*64 + t] = sm[k]*w;
            b += tm[k]*w;
        }
        gb[OFF_B2F + t] = b;
    }
}

// ---------------- launch ----------------
extern "C" void kernel_launch(void* const* d_in, const int* in_sizes, int n_in,
                              void* d_out, int out_size){
    (void)in_sizes; (void)n_in; (void)out_size;
    const float* x    = (const float*)d_in[0];
    const int*   ei   = (const int*)  d_in[1];
    const float* ea   = (const float*)d_in[2];
    const int*   esrc = (const int*)  d_in[3];
    const int*   etgt = (const int*)  d_in[4];
    const float* W1l  = (const float*)d_in[5];
    const float* b1   = (const float*)d_in[6];
    const float* W1r  = (const float*)d_in[7];
    const float* W2l  = (const float*)d_in[8];
    const float* b2   = (const float*)d_in[9];
    const float* W2r  = (const float*)d_in[10];
    const float* bn1g = (const float*)d_in[11];
    const float* bn1b = (const float*)d_in[12];
    const float* bn2g = (const float*)d_in[13];
    const float* bn2b = (const float*)d_in[14];
    const float* We   = (const float*)d_in[15];
    const float* be   = (const float*)d_in[16];
    const float* bneg = (const float*)d_in[17];
    const float* bneb = (const float*)d_in[18];
    const float* Wm1  = (const float*)d_in[19];
    const float* bm1  = (const float*)d_in[20];
    const float* bnmg = (const float*)d_in[21];
    const float* bnmb = (const float*)d_in[22];
    const float* Wm2  = (const float*)d_in[23];
    const float* bm2  = (const float*)d_in[24];
    const float* Wm3  = (const float*)d_in[25];
    const float* bm3  = (const float*)d_in[26];
    float* out = (float*)d_out;

    float* gb = nullptr;
    cudaGetSymbolAddress((void**)&gb, g_buf);

    const int* src = ei;
    const int* dst = ei + NE;

    float* agg1 = gb + OFF_AGG1;
    float* cnt  = gb + OFF_CNT;
    float* agg2 = gb + OFF_AGG2;
    float* st   = gb + OFF_STAT;
    float* bn1s = st + 0,   *bn1q = st + 128;
    float* bn2s = st + 256, *bn2q = st + 384;
    float* bnes = st + 512, *bneq = st + 640;
    float* bnms = st + 768, *bnmq = st + 896;

    // zero accumulators + stats
    cudaMemsetAsync(gb, 0, ZERO_FLOATS * sizeof(float), 0);

    k_copy_x<<<(NP*32 + 255)/256, 256>>>(x, gb + OFF_XP);
    k_prep_weights<<<(64*128 + 256*128 + 128*256 + 255)/256, 256>>>(W1l, W1r, W2l, W2r, Wm1, gb);

    // ---- layer 1 ----
    k_scatter1<<<(NE*8 + 255)/256, 256>>>(x, src, dst, agg1, cnt);
    k_mean<<<(NP*32 + 255)/256, 256>>>(gb + OFF_M1, agg1, cnt, NP*32, 32);
    gemm_k<64,128,8,8,1,true><<<dim3(NP/64,1), 128>>>(
        gb+OFF_M1, gb+OFF_XP, gb+OFF_WC1, 128, b1, gb+OFF_H1, 128, NND,
        nullptr, nullptr, nullptr, bn1s, bn1q, nullptr, nullptr, nullptr);
    k_bnapply<<<(NND*128 + 255)/256, 256>>>(gb+OFF_H1, NND, bn1s, bn1q, bn1g, bn1b);

    // ---- layer 2 ----
    k_scatter2<<<(NE*32 + 255)/256, 256>>>(gb+OFF_H1, src, dst, agg2);
    k_mean<<<(NP*128 + 255)/256, 256>>>(gb + OFF_M2, agg2, cnt, NP*128, 128);
    gemm_k<256,128,8,8,1,true><<<dim3(NP/64,1), 128>>>(
        gb+OFF_M2, gb+OFF_H1, gb+OFF_WC2, 128, b2, gb+OFF_H2, 128, NND,
        nullptr, nullptr, nullptr, bn2s, bn2q, nullptr, nullptr, nullptr);
    k_bnapply<<<(NND*128 + 255)/256, 256>>>(gb+OFF_H2, NND, bn2s, bn2q, bn2g, bn2b);

    // ---- node transforms u|v = h2 @ [Wm1_A | Wm1_B] ----
    gemm_k<128,128,8,8,0,false><<<dim3(NP/64,2), 128>>>(
        gb+OFF_H2, nullptr, gb+OFF_BUV, 256, nullptr, gb+OFF_UV, 256, NP,
        nullptr, nullptr, nullptr, nullptr, nullptr, nullptr, nullptr, nullptr);

    // ---- edge encoder: RE = relu(ea @ We + be), stats for bne ----
    gemm_k<16,128,8,8,2,false><<<dim3(NE/64,1), 128>>>(
        ea, nullptr, We, 128, be, gb+OFF_RE, 128, NE,
        nullptr, nullptr, nullptr, bnes, bneq, nullptr, nullptr, nullptr);
    k_prep_ef<<<1,128>>>(Wm1, bm1, bneg, bneb, gb);

    // ---- z1 = relu(RE @ Wm1C' + u[es] + v[et] + bm1'), stats for bnm ----
    gemm_k<128,128,8,8,3,false><<<dim3(NE/64,1), 128>>>(
        gb+OFF_RE, nullptr, gb+OFF_W1CF, 128, gb+OFF_BM1F, gb+OFF_Z1, 128, NE,
        esrc, etgt, gb+OFF_UV, bnms, bnmq, nullptr, nullptr, nullptr);
    k_prep_m<<<1,128>>>(Wm2, bm2, bnmg, bnmb, gb);

    // ---- out = relu(z1 @ Wm2' + b2') @ Wm3 + bm3 ----
    gemm_k<128,64,8,4,4,false><<<dim3(NE/64,1), 128>>>(
        gb+OFF_Z1, nullptr, gb+OFF_W2F, 64, gb+OFF_B2F, nullptr, 0, NE,
        nullptr, nullptr, nullptr, nullptr, nullptr, Wm3, bm3, out);
}

// round 9
// speedup vs baseline: 1.0697x; 1.0697x over previous
#include <cuda_runtime.h>
#include <cstdint>
#include <cstddef>

#define EPSV 1e-5f
constexpr int NND = 100000;   // nodes
constexpr int NE  = 800000;   // edges
constexpr int NP  = 100032;   // nodes padded to multiple of 64
constexpr int NB_SCAN = (NP + 2047) / 2048;   // 49 scan blocks

// ---------------- float scratch ----------------
constexpr size_t OFF_STAT = 0;                                // 1024 (zeroed)
constexpr size_t OFF_XP   = 1024;                             // NP*32
constexpr size_t OFF_M1   = OFF_XP  + (size_t)NP*32;          // NP*32
constexpr size_t OFF_H1   = OFF_M1  + (size_t)NP*32;          // NP*128
constexpr size_t OFF_M2   = OFF_H1  + (size_t)NP*128;         // NP*128
constexpr size_t OFF_H2   = OFF_M2  + (size_t)NP*128;         // NP*128
constexpr size_t OFF_UV   = OFF_H2  + (size_t)NP*128;         // NP*256
constexpr size_t OFF_RE   = OFF_UV  + (size_t)NP*256;         // NE*128
constexpr size_t OFF_Z1   = OFF_RE  + (size_t)NE*128;         // NE*128
constexpr size_t OFF_WC1  = OFF_Z1  + (size_t)NE*128;         // 64*128
constexpr size_t OFF_WC2  = OFF_WC1 + 64*128;                 // 256*128
constexpr size_t OFF_BUV  = OFF_WC2 + 256*128;                // 128*256
constexpr size_t OFF_W1CF = OFF_BUV + 128*256;                // 128*128
constexpr size_t OFF_BM1F = OFF_W1CF + 128*128;               // 128
constexpr size_t OFF_W2F  = OFF_BM1F + 128;                   // 128*64
constexpr size_t OFF_B2F  = OFF_W2F + 128*64;                 // 64
constexpr size_t GBUF_TOTAL = OFF_B2F + 64;

__device__ float g_buf[GBUF_TOTAL];

// ---------------- int scratch (CSR) ----------------
constexpr size_t IOFF_CNT  = 0;                 // NP (zeroed)
constexpr size_t IOFF_OFF  = IOFF_CNT + NP;     // NP
constexpr size_t IOFF_CUR  = IOFF_OFF + NP;     // NP
constexpr size_t IOFF_BSUM = IOFF_CUR + NP;     // 64
constexpr size_t IOFF_EL   = IOFF_BSUM + 64;    // NE
constexpr size_t IBUF_TOTAL = IOFF_EL + NE;

__device__ int g_ibuf[IBUF_TOTAL];

// ---------------- CSR build ----------------
__global__ void k_hist(const int* __restrict__ dst, int* __restrict__ cnt){
    int e = blockIdx.x*256 + threadIdx.x;
    if (e < NE) atomicAdd(&cnt[dst[e]], 1);
}

__global__ void k_blocksum(const int* __restrict__ cnt, int* __restrict__ bsum){
    __shared__ int sh[256];
    int base = blockIdx.x*2048 + threadIdx.x*8;
    int s = 0;
#pragma unroll
    for (int j=0;j<8;j++){ int i = base + j; if (i < NP) s += cnt[i]; }
    sh[threadIdx.x] = s; __syncthreads();
    for (int o=128;o>0;o>>=1){ if (threadIdx.x<o) sh[threadIdx.x]+=sh[threadIdx.x+o]; __syncthreads(); }
    if (threadIdx.x==0) bsum[blockIdx.x] = sh[0];
}

__global__ void k_scanb(int* __restrict__ bsum){
    __shared__ int sh[64];
    int t = threadIdx.x;
    int v = (t < NB_SCAN) ? bsum[t] : 0;
    sh[t] = v; __syncthreads();
    for (int o=1;o<64;o<<=1){
        int tmp = (t>=o) ? sh[t-o] : 0;
        __syncthreads();
        sh[t] += tmp;
        __syncthreads();
    }
    if (t < NB_SCAN) bsum[t] = sh[t] - v;   // exclusive
}

__global__ void k_offsets(const int* __restrict__ cnt, const int* __restrict__ bsum,
                          int* __restrict__ off, int* __restrict__ cur){
    __shared__ int sh[256];
    int base = blockIdx.x*2048 + threadIdx.x*8;
    int loc[8]; int s = 0;
#pragma unroll
    for (int j=0;j<8;j++){ int i = base + j; int c = (i<NP)?cnt[i]:0; loc[j]=s; s+=c; }
    sh[threadIdx.x] = s; __syncthreads();
    int v = s;
    for (int o=1;o<256;o<<=1){
        int tmp = (threadIdx.x>=o) ? sh[threadIdx.x-o] : 0;
        __syncthreads();
        sh[threadIdx.x] += tmp;
        __syncthreads();
    }
    int ex = sh[threadIdx.x] - v + bsum[blockIdx.x];
#pragma unroll
    for (int j=0;j<8;j++){
        int i = base + j;
        if (i < NP){ int o_ = ex + loc[j]; off[i]=o_; cur[i]=o_; }
    }
}

__global__ void k_fill(const int* __restrict__ src, const int* __restrict__ dst,
                       int* __restrict__ cur, int* __restrict__ elist){
    int e = blockIdx.x*256 + threadIdx.x;
    if (e >= NE) return;
    int p = atomicAdd(&cur[dst[e]], 1);
    elist[p] = src[e];
}

// ---------------- gather-based mean aggregation ----------------
// one warp per node; F=32: lane -> one float
__global__ void k_agg1(const float* __restrict__ x, const int* __restrict__ off,
                       const int* __restrict__ cnt, const int* __restrict__ elist,
                       float* __restrict__ m1){
    int w = (blockIdx.x*256 + threadIdx.x) >> 5;
    int lane = threadIdx.x & 31;
    if (w >= NP) return;
    int o = off[w], d = cnt[w];
    float s = 0.f;
    for (int j=0;j<d;j++){
        int sn = __ldg(&elist[o+j]);
        s += __ldg(&x[(size_t)sn*32 + lane]);
    }
    m1[(size_t)w*32 + lane] = s / fmaxf((float)d, 1.f);
}

// F=128: lane -> float4
__global__ void k_agg2(const float* __restrict__ h1, const int* __restrict__ off,
                       const int* __restrict__ cnt, const int* __restrict__ elist,
                       float* __restrict__ m2){
    int w = (blockIdx.x*256 + threadIdx.x) >> 5;
    int lane = threadIdx.x & 31;
    if (w >= NP) return;
    int o = off[w], d = cnt[w];
    float4 s = make_float4(0.f,0.f,0.f,0.f);
    for (int j=0;j<d;j++){
        int sn = __ldg(&elist[o+j]);
        float4 v = *reinterpret_cast<const float4*>(h1 + (size_t)sn*128 + lane*4);
        s.x += v.x; s.y += v.y; s.z += v.z; s.w += v.w;
    }
    float inv = 1.f / fmaxf((float)d, 1.f);
    s.x *= inv; s.y *= inv; s.z *= inv; s.w *= inv;
    *reinterpret_cast<float4*>(m2 + (size_t)w*128 + lane*4) = s;
}

// ---------------- generic register-blocked GEMM with fused epilogues ----------------
// EPI 0: +bias, store
// EPI 1: +bias, store, column stats (rows < Mreal)
// EPI 2: +bias, relu, store, stats
// EPI 3: +bias, + uv[es] + uv[et] gather, relu, store, stats
// EPI 4: +bias, relu, row-dot with wv, reduce, write outv
template<int K, int BN, int TM, int TN, int EPI, bool SPLITA>
__global__ void __launch_bounds__(128)
gemm_k(const float* __restrict__ A0, const float* __restrict__ A1,
       const float* __restrict__ B, int ldb,
       const float* __restrict__ bias,
       float* __restrict__ C, int ldc, int Mreal,
       const int* __restrict__ es, const int* __restrict__ et,
       const float* __restrict__ uv,
       float* __restrict__ gsum, float* __restrict__ gsq,
       const float* __restrict__ wv, const float* __restrict__ wb,
       float* __restrict__ outv)
{
    constexpr int BM = 64, BK = 16;
    constexpr int TCOLS = BN / TN;
    constexpr int LDA = SPLITA ? (K/2) : K;

    __shared__ float As[BK][BM + 4];
    __shared__ float Bs[BK][BN];
    __shared__ float s_sum[(EPI>=1 && EPI<=3) ? BN : 1];
    __shared__ float s_sq [(EPI>=1 && EPI<=3) ? BN : 1];
    __shared__ float s_red[(EPI==4) ? (BM*(TCOLS+1)) : 1];

    const int tid = threadIdx.x;
    const int row0 = blockIdx.x * BM;
    const int colblk = blockIdx.y * BN;

    float acc[TM][TN];
#pragma unroll
    for (int i=0;i<TM;i++)
#pragma unroll
        for (int j=0;j<TN;j++) acc[i][j]=0.f;

    const int tc = tid % TCOLS, tr = tid / TCOLS;

    for (int k0 = 0; k0 < K; k0 += BK) {
#pragma unroll
        for (int p = 0; p < 2; ++p) {
            int ar = (tid >> 2) + p*32;
            int ac = (tid & 3) * 4;
            int grow = row0 + ar;
            int gk = k0 + ac;
            const float* Ap = A0; int kk = gk;
            if (SPLITA && gk >= K/2) { Ap = A1; kk = gk - K/2; }
            float4 v = *reinterpret_cast<const float4*>(Ap + (size_t)grow*LDA + kk);
            As[ac+0][ar]=v.x; As[ac+1][ar]=v.y; As[ac+2][ar]=v.z; As[ac+3][ar]=v.w;
        }
        constexpr int BLD = (BK*BN)/(128*4);
#pragma unroll
        for (int p = 0; p < BLD; ++p) {
            int lin = tid + p*128;
            int br = lin / (BN/4);
            int bc = (lin % (BN/4)) * 4;
            float4 v = *reinterpret_cast<const float4*>(B + (size_t)(k0+br)*ldb + colblk + bc);
            *reinterpret_cast<float4*>(&Bs[br][bc]) = v;
        }
        __syncthreads();
#pragma unroll
        for (int kk = 0; kk < BK; ++kk) {
            float a[TM], b[TN];
#pragma unroll
            for (int i=0;i<TM;i++) a[i] = As[kk][tr*TM+i];
#pragma unroll
            for (int j=0;j<TN;j++) b[j] = Bs[kk][tc*TN+j];
#pragma unroll
            for (int i=0;i<TM;i++)
#pragma unroll
                for (int j=0;j<TN;j++) acc[i][j] = fmaf(a[i], b[j], acc[i][j]);
        }
        __syncthreads();
    }

    const int gc0 = colblk + tc*TN;
    float breg[TN];
#pragma unroll
    for (int j=0;j<TN;j++) breg[j] = bias ? bias[gc0+j] : 0.f;

    float cs[TN], cq[TN];
#pragma unroll
    for (int j=0;j<TN;j++){ cs[j]=0.f; cq[j]=0.f; }

    if constexpr (EPI == 0 || EPI == 1) {
#pragma unroll
        for (int i=0;i<TM;i++){
            int r = row0 + tr*TM + i;
#pragma unroll
            for (int j=0;j<TN;j++){
                float v = acc[i][j] + breg[j];
                C[(size_t)r*ldc + gc0 + j] = v;
                if (EPI==1 && r < Mreal){ cs[j]+=v; cq[j]+=v*v; }
            }
        }
    } else if constexpr (EPI == 2) {
#pragma unroll
        for (int i=0;i<TM;i++){
            int r = row0 + tr*TM + i;
#pragma unroll
            for (int j=0;j<TN;j++){
                float v = fmaxf(acc[i][j] + breg[j], 0.f);
                C[(size_t)r*ldc + gc0 + j] = v;
                if (r < Mreal){ cs[j]+=v; cq[j]+=v*v; }
            }
        }
    } else if constexpr (EPI == 3) {
#pragma unroll
        for (int i=0;i<TM;i++){
            int r = row0 + tr*TM + i;
            int e1 = es[r], e2 = et[r];
            const float* up = uv + (size_t)e1*256 + gc0;
            const float* vp = uv + (size_t)e2*256 + 128 + gc0;
#pragma unroll
            for (int j=0;j<TN;j++){
                float v = fmaxf(acc[i][j] + breg[j] + up[j] + vp[j], 0.f);
                C[(size_t)r*ldc + gc0 + j] = v;
                cs[j]+=v; cq[j]+=v*v;
            }
        }
    } else if constexpr (EPI == 4) {
        float wreg[TN];
#pragma unroll
        for (int j=0;j<TN;j++) wreg[j] = wv[gc0+j];
#pragma unroll
        for (int i=0;i<TM;i++){
            float p = 0.f;
#pragma unroll
            for (int j=0;j<TN;j++){
                float v = fmaxf(acc[i][j] + breg[j], 0.f);
                p = fmaf(v, wreg[j], p);
            }
            s_red[(tr*TM+i)*(TCOLS+1) + tc] = p;
        }
        __syncthreads();
        if (tid < BM){
            float s = 0.f;
#pragma unroll
            for (int t=0;t<TCOLS;t++) s += s_red[tid*(TCOLS+1)+t];
            outv[row0 + tid] = s + wb[0];
        }
    }

    if constexpr (EPI >= 1 && EPI <= 3) {
        for (int i=tid;i<BN;i+=128){ s_sum[i]=0.f; s_sq[i]=0.f; }
        __syncthreads();
#pragma unroll
        for (int j=0;j<TN;j++){
            atomicAdd(&s_sum[tc*TN+j], cs[j]);
            atomicAdd(&s_sq [tc*TN+j], cq[j]);
        }
        __syncthreads();
        for (int i=tid;i<BN;i+=128){
            atomicAdd(&gsum[colblk+i], s_sum[i]);
            atomicAdd(&gsq [colblk+i], s_sq[i]);
        }
    }
}

// ---------------- elementwise / prep kernels ----------------
__global__ void k_copy_x(const float* __restrict__ x, float* __restrict__ xp){
    int i = blockIdx.x*256 + threadIdx.x;
    if (i < NP*32) xp[i] = (i < NND*32) ? x[i] : 0.f;
}

__global__ void k_prep_weights(const float* __restrict__ W1l, const float* __restrict__ W1r,
                               const float* __restrict__ W2l, const float* __restrict__ W2r,
                               const float* __restrict__ Wm1, float* __restrict__ gb){
    int i = blockIdx.x*256 + threadIdx.x;
    if (i < 64*128){
        int r = i>>7, c = i&127;
        gb[OFF_WC1 + i] = (r<32) ? W1l[r*128+c] : W1r[(r-32)*128+c];
    } else if (i < 64*128 + 256*128){
        int j = i - 64*128; int r = j>>7, c = j&127;
        gb[OFF_WC2 + j] = (r<128) ? W2l[r*128+c] : W2r[(r-128)*128+c];
    } else if (i < 64*128 + 256*128 + 128*256){
        int j = i - 64*128 - 256*128; int k = j>>8, c = j&255;
        gb[OFF_BUV + j] = (c<128) ? Wm1[k*128+c] : Wm1[(128+k)*128 + (c-128)];
    }
}

__global__ void k_bnapply(float* __restrict__ buf, int n,
                          const float* __restrict__ ss, const float* __restrict__ sq,
                          const float* __restrict__ g, const float* __restrict__ b){
    int i = blockIdx.x*256 + threadIdx.x;
    if (i >= n*128) return;
    int c = i & 127;
    float m = ss[c] / (float)n;
    float var = sq[c] / (float)n - m*m;
    float s = g[c] * rsqrtf(var + EPSV);
    float v = buf[i]*s + (b[c] - m*s);
    buf[i] = fmaxf(v, 0.f);
}

__global__ void k_prep_ef(const float* __restrict__ Wm1, const float* __restrict__ bm1,
                          const float* __restrict__ bg, const float* __restrict__ bb,
                          float* __restrict__ gb){
    __shared__ float se[128], te[128];
    int t = threadIdx.x;
    float m = gb[OFF_STAT + 512 + t] / (float)NE;
    float var = gb[OFF_STAT + 640 + t] / (float)NE - m*m;
    float s = bg[t] * rsqrtf(var + EPSV);
    se[t] = s; te[t] = bb[t] - m*s;
    __syncthreads();
    float bacc = bm1[t];
    for (int k = 0; k < 128; ++k){
        float w = Wm1[(size_t)(256+k)*128 + t];
        gb[OFF_W1CF + k*128 + t] = se[k]*w;
        bacc += te[k]*w;
    }
    gb[OFF_BM1F + t] = bacc;
}

__global__ void k_prep_m(const float* __restrict__ Wm2, const float* __restrict__ bm2,
                         const float* __restrict__ bg, const float* __restrict__ bb,
                         float* __restrict__ gb){
    __shared__ float sm[128], tm[128];
    int t = threadIdx.x;
    float m = gb[OFF_STAT + 768 + t] / (float)NE;
    float var = gb[OFF_STAT + 896 + t] / (float)NE - m*m;
    float s = bg[t] * rsqrtf(var + EPSV);
    sm[t] = s; tm[t] = bb[t] - m*s;
    __syncthreads();
    if (t < 64){
        float b = bm2[t];
        for (int k = 0; k < 128; ++k){
            float w = Wm2[k*64 + t];
            b += tm[k]*w;
            gb[OFF_W2F + k*64 + t] = sm[k]*w;
        }
        gb[OFF_B2F + t] = b;
    }
}

// ---------------- launch ----------------
extern "C" void kernel_launch(void* const* d_in, const int* in_sizes, int n_in,
                              void* d_out, int out_size){
    (void)in_sizes; (void)n_in; (void)out_size;
    const float* x    = (const float*)d_in[0];
    const int*   ei   = (const int*)  d_in[1];
    const float* ea   = (const float*)d_in[2];
    const int*   esrc = (const int*)  d_in[3];
    const int*   etgt = (const int*)  d_in[4];
    const float* W1l  = (const float*)d_in[5];
    const float* b1   = (const float*)d_in[6];
    const float* W1r  = (const float*)d_in[7];
    const float* W2l  = (const float*)d_in[8];
    const float* b2   = (const float*)d_in[9];
    const float* W2r  = (const float*)d_in[10];
    const float* bn1g = (const float*)d_in[11];
    const float* bn1b = (const float*)d_in[12];
    const float* bn2g = (const float*)d_in[13];
    const float* bn2b = (const float*)d_in[14];
    const float* We   = (const float*)d_in[15];
    const float* be   = (const float*)d_in[16];
    const float* bneg = (const float*)d_in[17];
    const float* bneb = (const float*)d_in[18];
    const float* Wm1  = (const float*)d_in[19];
    const float* bm1  = (const float*)d_in[20];
    const float* bnmg = (const float*)d_in[21];
    const float* bnmb = (const float*)d_in[22];
    const float* Wm2  = (const float*)d_in[23];
    const float* bm2  = (const float*)d_in[24];
    const float* Wm3  = (const float*)d_in[25];
    const float* bm3  = (const float*)d_in[26];
    float* out = (float*)d_out;

    float* gb = nullptr;
    cudaGetSymbolAddress((void**)&gb, g_buf);
    int* ib = nullptr;
    cudaGetSymbolAddress((void**)&ib, g_ibuf);

    const int* src = ei;
    const int* dst = ei + NE;

    int* csr_cnt = ib + IOFF_CNT;
    int* csr_off = ib + IOFF_OFF;
    int* csr_cur = ib + IOFF_CUR;
    int* csr_bs  = ib + IOFF_BSUM;
    int* csr_el  = ib + IOFF_EL;

    float* st   = gb + OFF_STAT;
    float* bn1s = st + 0,   *bn1q = st + 128;
    float* bn2s = st + 256, *bn2q = st + 384;
    float* bnes = st + 512, *bneq = st + 640;
    float* bnms = st + 768, *bnmq = st + 896;

    // zero stats + CSR counters
    cudaMemsetAsync(gb, 0, 1024 * sizeof(float), 0);
    cudaMemsetAsync(csr_cnt, 0, NP * sizeof(int), 0);

    k_copy_x<<<(NP*32 + 255)/256, 256>>>(x, gb + OFF_XP);
    k_prep_weights<<<(64*128 + 256*128 + 128*256 + 255)/256, 256>>>(W1l, W1r, W2l, W2r, Wm1, gb);

    // ---- CSR build (shared by both SAGE layers) ----
    k_hist<<<(NE + 255)/256, 256>>>(dst, csr_cnt);
    k_blocksum<<<NB_SCAN, 256>>>(csr_cnt, csr_bs);
    k_scanb<<<1, 64>>>(csr_bs);
    k_offsets<<<NB_SCAN, 256>>>(csr_cnt, csr_bs, csr_off, csr_cur);
    k_fill<<<(NE + 255)/256, 256>>>(src, dst, csr_cur, csr_el);

    // ---- layer 1 ----
    k_agg1<<<(NP*32 + 255)/256, 256>>>(x, csr_off, csr_cnt, csr_el, gb + OFF_M1);
    gemm_k<64,128,8,8,1,true><<<dim3(NP/64,1), 128>>>(
        gb+OFF_M1, gb+OFF_XP, gb+OFF_WC1, 128, b1, gb+OFF_H1, 128, NND,
        nullptr, nullptr, nullptr, bn1s, bn1q, nullptr, nullptr, nullptr);
    k_bnapply<<<(NND*128 + 255)/256, 256>>>(gb+OFF_H1, NND, bn1s, bn1q, bn1g, bn1b);

    // ---- layer 2 ----
    k_agg2<<<(NP*32 + 255)/256, 256>>>(gb+OFF_H1, csr_off, csr_cnt, csr_el, gb + OFF_M2);
    gemm_k<256,128,8,8,1,true><<<dim3(NP/64,1), 128>>>(
        gb+OFF_M2, gb+OFF_H1, gb+OFF_WC2, 128, b2, gb+OFF_H2, 128, NND,
        nullptr, nullptr, nullptr, bn2s, bn2q, nullptr, nullptr, nullptr);
    k_bnapply<<<(NND*128 + 255)/256, 256>>>(gb+OFF_H2, NND, bn2s, bn2q, bn2g, bn2b);

    // ---- node transforms u|v = h2 @ [Wm1_A | Wm1_B] ----
    gemm_k<128,128,8,8,0,false><<<dim3(NP/64,2), 128>>>(
        gb+OFF_H2, nullptr, gb+OFF_BUV, 256, nullptr, gb+OFF_UV, 256, NP,
        nullptr, nullptr, nullptr, nullptr, nullptr, nullptr, nullptr, nullptr);

    // ---- edge encoder: RE = relu(ea @ We + be), stats for bne ----
    gemm_k<16,128,8,8,2,false><<<dim3(NE/64,1), 128>>>(
        ea, nullptr, We, 128, be, gb+OFF_RE, 128, NE,
        nullptr, nullptr, nullptr, bnes, bneq, nullptr, nullptr, nullptr);
    k_prep_ef<<<1,128>>>(Wm1, bm1, bneg, bneb, gb);

    // ---- z1 = relu(RE @ Wm1C' + u[es] + v[et] + bm1'), stats for bnm ----
    gemm_k<128,128,8,8,3,false><<<dim3(NE/64,1), 128>>>(
        gb+OFF_RE, nullptr, gb+OFF_W1CF, 128, gb+OFF_BM1F, gb+OFF_Z1, 128, NE,
        esrc, etgt, gb+OFF_UV, bnms, bnmq, nullptr, nullptr, nullptr);
    k_prep_m<<<1,128>>>(Wm2, bm2, bnmg, bnmb, gb);

    // ---- out = relu(z1 @ Wm2' + b2') @ Wm3 + bm3 ----
    gemm_k<128,64,8,4,4,false><<<dim3(NE/64,1), 128>>>(
        gb+OFF_Z1, nullptr, gb+OFF_W2F, 64, gb+OFF_B2F, nullptr, 0, NE,
        nullptr, nullptr, nullptr, nullptr, nullptr, Wm3, bm3, out);
}

// round 12
// speedup vs baseline: 1.3526x; 1.2644x over previous
#include <cuda_runtime.h>
#include <cstdint>
#include <cstddef>

#define EPSV 1e-5f
constexpr int NND = 100000;   // nodes
constexpr int NE  = 800000;   // edges
constexpr int NP  = 100032;   // nodes padded to multiple of 64
constexpr int NB_SCAN = (NP + 2047) / 2048;   // 49 scan blocks

// ---------------- float scratch ----------------
constexpr size_t OFF_STAT = 0;                                // 1024 (zeroed)
constexpr size_t OFF_XP   = 1024;                             // NP*32
constexpr size_t OFF_M1   = OFF_XP  + (size_t)NP*32;          // NP*32
constexpr size_t OFF_H1   = OFF_M1  + (size_t)NP*32;          // NP*128
constexpr size_t OFF_M2   = OFF_H1  + (size_t)NP*128;         // NP*128
constexpr size_t OFF_H2   = OFF_M2  + (size_t)NP*128;         // NP*128
constexpr size_t OFF_UV   = OFF_H2  + (size_t)NP*128;         // NP*256
constexpr size_t OFF_RE   = OFF_UV  + (size_t)NP*256;         // NE*128
constexpr size_t OFF_Z1   = OFF_RE  + (size_t)NE*128;         // NE*128
constexpr size_t OFF_WC1  = OFF_Z1  + (size_t)NE*128;         // 64*128
constexpr size_t OFF_WC2  = OFF_WC1 + 64*128;                 // 256*128
constexpr size_t OFF_BUV  = OFF_WC2 + 256*128;                // 128*256
constexpr size_t OFF_BFRAG= OFF_BUV + 128*256;                // 16384 (tf32 B fragments)
constexpr size_t OFF_BM1F = OFF_BFRAG + 128*128;              // 128
constexpr size_t OFF_W2F  = OFF_BM1F + 128;                   // 128*64
constexpr size_t OFF_B2F  = OFF_W2F + 128*64;                 // 64
constexpr size_t GBUF_TOTAL = OFF_B2F + 64;

__device__ float g_buf[GBUF_TOTAL];

// ---------------- int scratch (CSR) ----------------
constexpr size_t IOFF_CNT  = 0;                 // NP (zeroed)
constexpr size_t IOFF_OFF  = IOFF_CNT + NP;     // NP
constexpr size_t IOFF_CUR  = IOFF_OFF + NP;     // NP
constexpr size_t IOFF_BSUM = IOFF_CUR + NP;     // 64
constexpr size_t IOFF_EL   = IOFF_BSUM + 64;    // NE
constexpr size_t IBUF_TOTAL = IOFF_EL + NE;

__device__ int g_ibuf[IBUF_TOTAL];

// ---------------- tf32 helpers ----------------
__device__ __forceinline__ uint32_t tf32u(float x){
    uint32_t u;
    asm("cvt.rna.tf32.f32 %0, %1;" : "=r"(u) : "f"(x));
    return u;
}
__device__ __forceinline__ float to_tf32f(float x){
    return __uint_as_float(tf32u(x));
}

// legacy tensor-core mma (HMMA path; supported on base sm_103 target)
__device__ __forceinline__ void mma16n8k8(float* d, const uint32_t* a, const uint32_t* b){
    asm volatile(
        "mma.sync.aligned.m16n8k8.row.col.f32.tf32.tf32.f32 "
        "{%0,%1,%2,%3}, {%4,%5,%6,%7}, {%8,%9}, {%0,%1,%2,%3};"
        : "+f"(d[0]), "+f"(d[1]), "+f"(d[2]), "+f"(d[3])
        : "r"(a[0]), "r"(a[1]), "r"(a[2]), "r"(a[3]), "r"(b[0]), "r"(b[1]));
}

// ---------------- CSR build ----------------
__global__ void k_hist(const int* __restrict__ dst, int* __restrict__ cnt){
    int e = blockIdx.x*256 + threadIdx.x;
    if (e < NE) atomicAdd(&cnt[dst[e]], 1);
}

__global__ void k_blocksum(const int* __restrict__ cnt, int* __restrict__ bsum){
    __shared__ int sh[256];
    int base = blockIdx.x*2048 + threadIdx.x*8;
    int s = 0;
#pragma unroll
    for (int j=0;j<8;j++){ int i = base + j; if (i < NP) s += cnt[i]; }
    sh[threadIdx.x] = s; __syncthreads();
    for (int o=128;o>0;o>>=1){ if (threadIdx.x<o) sh[threadIdx.x]+=sh[threadIdx.x+o]; __syncthreads(); }
    if (threadIdx.x==0) bsum[blockIdx.x] = sh[0];
}

__global__ void k_scanb(int* __restrict__ bsum){
    __shared__ int sh[64];
    int t = threadIdx.x;
    int v = (t < NB_SCAN) ? bsum[t] : 0;
    sh[t] = v; __syncthreads();
    for (int o=1;o<64;o<<=1){
        int tmp = (t>=o) ? sh[t-o] : 0;
        __syncthreads();
        sh[t] += tmp;
        __syncthreads();
    }
    if (t < NB_SCAN) bsum[t] = sh[t] - v;   // exclusive
}

__global__ void k_offsets(const int* __restrict__ cnt, const int* __restrict__ bsum,
                          int* __restrict__ off, int* __restrict__ cur){
    __shared__ int sh[256];
    int base = blockIdx.x*2048 + threadIdx.x*8;
    int loc[8]; int s = 0;
#pragma unroll
    for (int j=0;j<8;j++){ int i = base + j; int c = (i<NP)?cnt[i]:0; loc[j]=s; s+=c; }
    sh[threadIdx.x] = s; __syncthreads();
    int v = s;
    for (int o=1;o<256;o<<=1){
        int tmp = (threadIdx.x>=o) ? sh[threadIdx.x-o] : 0;
        __syncthreads();
        sh[threadIdx.x] += tmp;
        __syncthreads();
    }
    int ex = sh[threadIdx.x] - v + bsum[blockIdx.x];
#pragma unroll
    for (int j=0;j<8;j++){
        int i = base + j;
        if (i < NP){ int o_ = ex + loc[j]; off[i]=o_; cur[i]=o_; }
    }
}

__global__ void k_fill(const int* __restrict__ src, const int* __restrict__ dst,
                       int* __restrict__ cur, int* __restrict__ elist){
    int e = blockIdx.x*256 + threadIdx.x;
    if (e >= NE) return;
    int p = atomicAdd(&cur[dst[e]], 1);
    elist[p] = src[e];
}

// ---------------- gather-based mean aggregation ----------------
__global__ void k_agg1(const float* __restrict__ x, const int* __restrict__ off,
                       const int* __restrict__ cnt, const int* __restrict__ elist,
                       float* __restrict__ m1){
    int w = (blockIdx.x*256 + threadIdx.x) >> 5;
    int lane = threadIdx.x & 31;
    if (w >= NP) return;
    int o = off[w], d = cnt[w];
    float s = 0.f;
    for (int j=0;j<d;j++){
        int sn = __ldg(&elist[o+j]);
        s += __ldg(&x[(size_t)sn*32 + lane]);
    }
    m1[(size_t)w*32 + lane] = s / fmaxf((float)d, 1.f);
}

__global__ void k_agg2(const float* __restrict__ h1, const int* __restrict__ off,
                       const int* __restrict__ cnt, const int* __restrict__ elist,
                       float* __restrict__ m2){
    int w = (blockIdx.x*256 + threadIdx.x) >> 5;
    int lane = threadIdx.x & 31;
    if (w >= NP) return;
    int o = off[w], d = cnt[w];
    float4 s = make_float4(0.f,0.f,0.f,0.f);
    for (int j=0;j<d;j++){
        int sn = __ldg(&elist[o+j]);
        float4 v = *reinterpret_cast<const float4*>(h1 + (size_t)sn*128 + lane*4);
        s.x += v.x; s.y += v.y; s.z += v.z; s.w += v.w;
    }
    float inv = 1.f / fmaxf((float)d, 1.f);
    s.x *= inv; s.y *= inv; s.z *= inv; s.w *= inv;
    *reinterpret_cast<float4*>(m2 + (size_t)w*128 + lane*4) = s;
}

// ---------------- generic register-blocked GEMM with fused epilogues ----------------
// EPI 0: +bias, store
// EPI 1: +bias, store, column stats (rows < Mreal)
// EPI 2: +bias, relu, store, stats
// EPI 4: +bias, relu, row-dot with wv, reduce, write outv
template<int K, int BN, int TM, int TN, int EPI, bool SPLITA>
__global__ void __launch_bounds__(128)
gemm_k(const float* __restrict__ A0, const float* __restrict__ A1,
       const float* __restrict__ B, int ldb,
       const float* __restrict__ bias,
       float* __restrict__ C, int ldc, int Mreal,
       float* __restrict__ gsum, float* __restrict__ gsq,
       const float* __restrict__ wv, const float* __restrict__ wb,
       float* __restrict__ outv)
{
    constexpr int BM = 64, BK = 16;
    constexpr int TCOLS = BN / TN;
    constexpr int LDA = SPLITA ? (K/2) : K;

    __shared__ float As[BK][BM + 4];
    __shared__ float Bs[BK][BN];
    __shared__ float s_sum[(EPI>=1 && EPI<=2) ? BN : 1];
    __shared__ float s_sq [(EPI>=1 && EPI<=2) ? BN : 1];
    __shared__ float s_red[(EPI==4) ? (BM*(TCOLS+1)) : 1];

    const int tid = threadIdx.x;
    const int row0 = blockIdx.x * BM;
    const int colblk = blockIdx.y * BN;

    float acc[TM][TN];
#pragma unroll
    for (int i=0;i<TM;i++)
#pragma unroll
        for (int j=0;j<TN;j++) acc[i][j]=0.f;

    const int tc = tid % TCOLS, tr = tid / TCOLS;

    for (int k0 = 0; k0 < K; k0 += BK) {
#pragma unroll
        for (int p = 0; p < 2; ++p) {
            int ar = (tid >> 2) + p*32;
            int ac = (tid & 3) * 4;
            int grow = row0 + ar;
            int gk = k0 + ac;
            const float* Ap = A0; int kk = gk;
            if (SPLITA && gk >= K/2) { Ap = A1; kk = gk - K/2; }
            float4 v = *reinterpret_cast<const float4*>(Ap + (size_t)grow*LDA + kk);
            As[ac+0][ar]=v.x; As[ac+1][ar]=v.y; As[ac+2][ar]=v.z; As[ac+3][ar]=v.w;
        }
        constexpr int BLD = (BK*BN)/(128*4);
#pragma unroll
        for (int p = 0; p < BLD; ++p) {
            int lin = tid + p*128;
            int br = lin / (BN/4);
            int bc = (lin % (BN/4)) * 4;
            float4 v = *reinterpret_cast<const float4*>(B + (size_t)(k0+br)*ldb + colblk + bc);
            *reinterpret_cast<float4*>(&Bs[br][bc]) = v;
        }
        __syncthreads();
#pragma unroll
        for (int kk = 0; kk < BK; ++kk) {
            float a[TM], b[TN];
#pragma unroll
            for (int i=0;i<TM;i++) a[i] = As[kk][tr*TM+i];
#pragma unroll
            for (int j=0;j<TN;j++) b[j] = Bs[kk][tc*TN+j];
#pragma unroll
            for (int i=0;i<TM;i++)
#pragma unroll
                for (int j=0;j<TN;j++) acc[i][j] = fmaf(a[i], b[j], acc[i][j]);
        }
        __syncthreads();
    }

    const int gc0 = colblk + tc*TN;
    float breg[TN];
#pragma unroll
    for (int j=0;j<TN;j++) breg[j] = bias ? bias[gc0+j] : 0.f;

    float cs[TN], cq[TN];
#pragma unroll
    for (int j=0;j<TN;j++){ cs[j]=0.f; cq[j]=0.f; }

    if constexpr (EPI == 0 || EPI == 1) {
#pragma unroll
        for (int i=0;i<TM;i++){
            int r = row0 + tr*TM + i;
#pragma unroll
            for (int j=0;j<TN;j++){
                float v = acc[i][j] + breg[j];
                C[(size_t)r*ldc + gc0 + j] = v;
                if (EPI==1 && r < Mreal){ cs[j]+=v; cq[j]+=v*v; }
            }
        }
    } else if constexpr (EPI == 2) {
#pragma unroll
        for (int i=0;i<TM;i++){
            int r = row0 + tr*TM + i;
#pragma unroll
            for (int j=0;j<TN;j++){
                float v = fmaxf(acc[i][j] + breg[j], 0.f);
                C[(size_t)r*ldc + gc0 + j] = v;
                if (r < Mreal){ cs[j]+=v; cq[j]+=v*v; }
            }
        }
    } else if constexpr (EPI == 4) {
        float wreg[TN];
#pragma unroll
        for (int j=0;j<TN;j++) wreg[j] = wv[gc0+j];
#pragma unroll
        for (int i=0;i<TM;i++){
            float p = 0.f;
#pragma unroll
            for (int j=0;j<TN;j++){
                float v = fmaxf(acc[i][j] + breg[j], 0.f);
                p = fmaf(v, wreg[j], p);
            }
            s_red[(tr*TM+i)*(TCOLS+1) + tc] = p;
        }
        __syncthreads();
        if (tid < BM){
            float s = 0.f;
#pragma unroll
            for (int t=0;t<TCOLS;t++) s += s_red[tid*(TCOLS+1)+t];
            outv[row0 + tid] = s + wb[0];
        }
    }

    if constexpr (EPI >= 1 && EPI <= 2) {
        for (int i=tid;i<BN;i+=128){ s_sum[i]=0.f; s_sq[i]=0.f; }
        __syncthreads();
#pragma unroll
        for (int j=0;j<TN;j++){
            atomicAdd(&s_sum[tc*TN+j], cs[j]);
            atomicAdd(&s_sq [tc*TN+j], cq[j]);
        }
        __syncthreads();
        for (int i=tid;i<BN;i+=128){
            atomicAdd(&gsum[colblk+i], s_sum[i]);
            atomicAdd(&gsq [colblk+i], s_sq[i]);
        }
    }
}

// ---------------- z1 via legacy tensor-core mma (tf32) ----------------
// z1[r, n] = relu( sum_k RE[r,k]*Bf[k][n] + bias[n] + uv[es[r],n] + uv[et[r],128+n] )
// Bf precomputed in m16n8k8 fragment-major layout by k_prep_ef.
constexpr int Z_LDA = 68;   // smem row stride (floats): 68%32==4 -> conflict-free frags

__global__ void __launch_bounds__(256)
z1_mma(const float* __restrict__ RE, const float* __restrict__ Bf,
       const float* __restrict__ bias, const int* __restrict__ es, const int* __restrict__ et,
       const float* __restrict__ uv, float* __restrict__ z1)
{
    __shared__ float As[128 * Z_LDA + 4];
    const int tid = threadIdx.x;
    const int w = tid >> 5;
    const int lane = tid & 31;
    const int g = lane >> 2;        // groupID
    const int t = lane & 3;         // threadID_in_group
    const int wm = w >> 1;          // 0..3   (32-row strip)
    const int wn = w & 1;           // 0..1   (64-col strip)
    const int R  = wm * 32;
    const int Cn = wn * 64;
    const int row0 = blockIdx.x * 128;

    float acc[2][8][4];
#pragma unroll
    for (int i=0;i<2;i++)
#pragma unroll
        for (int j=0;j<8;j++)
#pragma unroll
            for (int q=0;q<4;q++) acc[i][j][q]=0.f;

    for (int c = 0; c < 2; ++c) {
        // stage RE chunk [128 rows][64 k], tf32-rounded
#pragma unroll
        for (int p = 0; p < 8; ++p) {
            int fid = tid + p*256;          // 0..2047 float4s
            int row = fid >> 4;
            int c4  = (fid & 15) * 4;
            float4 v = *reinterpret_cast<const float4*>(RE + (size_t)(row0+row)*128 + c*64 + c4);
            float* dstp = &As[row*Z_LDA + c4];
            dstp[0] = __uint_as_float(tf32u(v.x));
            dstp[1] = __uint_as_float(tf32u(v.y));
            dstp[2] = __uint_as_float(tf32u(v.z));
            dstp[3] = __uint_as_float(tf32u(v.w));
        }
        __syncthreads();

#pragma unroll
        for (int ks = 0; ks < 8; ++ks) {
            int kb = ks * 8;
            uint32_t a[2][4];
#pragma unroll
            for (int mt = 0; mt < 2; ++mt) {
                int rb = R + mt*16 + g;
                a[mt][0] = __float_as_uint(As[(rb    )*Z_LDA + kb + t    ]);
                a[mt][1] = __float_as_uint(As[(rb + 8)*Z_LDA + kb + t    ]);
                a[mt][2] = __float_as_uint(As[(rb    )*Z_LDA + kb + t + 4]);
                a[mt][3] = __float_as_uint(As[(rb + 8)*Z_LDA + kb + t + 4]);
            }
            int ksg = c*8 + ks;
#pragma unroll
            for (int nt = 0; nt < 8; ++nt) {
                int gnt = wn*8 + nt;
                float2 bb = *reinterpret_cast<const float2*>(Bf + ((size_t)(ksg*16 + gnt)*32 + lane)*2);
                uint32_t b[2] = { __float_as_uint(bb.x), __float_as_uint(bb.y) };
                mma16n8k8(acc[0][nt], a[0], b);
                mma16n8k8(acc[1][nt], a[1], b);
            }
        }
        __syncthreads();
    }

    // epilogue: c0,c1 -> row rb+g, cols 2t,2t+1 ; c2,c3 -> row rb+g+8
#pragma unroll
    for (int mt = 0; mt < 2; ++mt) {
        int r_lo = row0 + R + mt*16 + g;
        int r_hi = r_lo + 8;
        int e1a = es[r_lo], e2a = et[r_lo];
        int e1b = es[r_hi], e2b = et[r_hi];
        const float* ua = uv + (size_t)e1a*256;
        const float* va = uv + (size_t)e2a*256 + 128;
        const float* ub = uv + (size_t)e1b*256;
        const float* vb = uv + (size_t)e2b*256 + 128;
#pragma unroll
        for (int nt = 0; nt < 8; ++nt) {
            int col = Cn + nt*8 + 2*t;
            float2 bi = *reinterpret_cast<const float2*>(bias + col);
            float2 u1 = *reinterpret_cast<const float2*>(ua + col);
            float2 v1 = *reinterpret_cast<const float2*>(va + col);
            float2 u2 = *reinterpret_cast<const float2*>(ub + col);
            float2 v2 = *reinterpret_cast<const float2*>(vb + col);
            float2 olo, ohi;
            olo.x = fmaxf(acc[mt][nt][0] + bi.x + u1.x + v1.x, 0.f);
            olo.y = fmaxf(acc[mt][nt][1] + bi.y + u1.y + v1.y, 0.f);
            ohi.x = fmaxf(acc[mt][nt][2] + bi.x + u2.x + v2.x, 0.f);
            ohi.y = fmaxf(acc[mt][nt][3] + bi.y + u2.y + v2.y, 0.f);
            *reinterpret_cast<float2*>(z1 + (size_t)r_lo*128 + col) = olo;
            *reinterpret_cast<float2*>(z1 + (size_t)r_hi*128 + col) = ohi;
        }
    }
}

// ---------------- column stats over z1 (for bnm fold) ----------------
__global__ void k_colstats(const float* __restrict__ z1,
                           float* __restrict__ gsum, float* __restrict__ gsq){
    __shared__ float ss[256], sq[256];
    int col = threadIdx.x & 127;
    int half = threadIdx.x >> 7;     // 0 or 1
    size_t rbase = (size_t)blockIdx.x * 256 + half;
    float s = 0.f, q = 0.f;
#pragma unroll 4
    for (int i = 0; i < 128; ++i) {
        float v = __ldg(&z1[(rbase + (size_t)i*2) * 128 + col]);
        s += v; q += v*v;
    }
    ss[threadIdx.x] = s; sq[threadIdx.x] = q;
    __syncthreads();
    if (threadIdx.x < 128) {
        atomicAdd(&gsum[col], ss[threadIdx.x] + ss[threadIdx.x + 128]);
        atomicAdd(&gsq [col], sq[threadIdx.x] + sq[threadIdx.x + 128]);
    }
}

// ---------------- elementwise / prep kernels ----------------
__global__ void k_copy_x(const float* __restrict__ x, float* __restrict__ xp){
    int i = blockIdx.x*256 + threadIdx.x;
    if (i < NP*32) xp[i] = (i < NND*32) ? x[i] : 0.f;
}

__global__ void k_prep_weights(const float* __restrict__ W1l, const float* __restrict__ W1r,
                               const float* __restrict__ W2l, const float* __restrict__ W2r,
                               const float* __restrict__ Wm1, float* __restrict__ gb){
    int i = blockIdx.x*256 + threadIdx.x;
    if (i < 64*128){
        int r = i>>7, c = i&127;
        gb[OFF_WC1 + i] = (r<32) ? W1l[r*128+c] : W1r[(r-32)*128+c];
    } else if (i < 64*128 + 256*128){
        int j = i - 64*128; int r = j>>7, c = j&127;
        gb[OFF_WC2 + j] = (r<128) ? W2l[r*128+c] : W2r[(r-128)*128+c];
    } else if (i < 64*128 + 256*128 + 128*256){
        int j = i - 64*128 - 256*128; int k = j>>8, c = j&255;
        gb[OFF_BUV + j] = (c<128) ? Wm1[k*128+c] : Wm1[(128+k)*128 + (c-128)];
    }
}

__global__ void k_bnapply(float* __restrict__ buf, int n,
                          const float* __restrict__ ss, const float* __restrict__ sq,
                          const float* __restrict__ g, const float* __restrict__ b){
    int i = blockIdx.x*256 + threadIdx.x;
    if (i >= n*128) return;
    int c = i & 127;
    float m = ss[c] / (float)n;
    float var = sq[c] / (float)n - m*m;
    float s = g[c] * rsqrtf(var + EPSV);
    float v = buf[i]*s + (b[c] - m*s);
    buf[i] = fmaxf(v, 0.f);
}

// fold ef-BN into Wm1_C; emit bias and B in mma fragment-major tf32 layout
__global__ void k_prep_ef(const float* __restrict__ Wm1, const float* __restrict__ bm1,
                          const float* __restrict__ bg, const float* __restrict__ bb,
                          float* __restrict__ gb){
    __shared__ float se[128], te[128];
    int t = threadIdx.x;   // output column n
    float m = gb[OFF_STAT + 512 + t] / (float)NE;
    float var = gb[OFF_STAT + 640 + t] / (float)NE - m*m;
    float s = bg[t] * rsqrtf(var + EPSV);
    se[t] = s; te[t] = bb[t] - m*s;
    __syncthreads();
    float bacc = bm1[t];
    for (int k = 0; k < 128; ++k){
        bacc += te[k] * Wm1[(size_t)(256+k)*128 + t];
    }
    gb[OFF_BM1F + t] = bacc;
    // B fragments: lin = ((ks*16 + nt)*32 + lane)*2 + r
    // n = nt*8 + lane/4 ; k = ks*8 + (lane&3) + 4r ; value = se[k]*Wm1[256+k][n]
    for (int j = 0; j < 128; ++j){
        int lin = t*128 + j;
        int r    = lin & 1;
        int lane = (lin >> 1) & 31;
        int nt   = (lin >> 6) & 15;
        int ks   = lin >> 10;
        int n = nt*8 + (lane >> 2);
        int k = ks*8 + (lane & 3) + 4*r;
        gb[OFF_BFRAG + lin] = to_tf32f(se[k] * Wm1[(size_t)(256+k)*128 + n]);
    }
}

// fold bnm (stats over z1) into Wm2 and bias
__global__ void k_prep_m(const float* __restrict__ Wm2, const float* __restrict__ bm2,
                         const float* __restrict__ bg, const float* __restrict__ bb,
                         float* __restrict__ gb){
    __shared__ float sm[128], tm[128];
    int t = threadIdx.x;
    float m = gb[OFF_STAT + 768 + t] / (float)NE;
    float var = gb[OFF_STAT + 896 + t] / (float)NE - m*m;
    float s = bg[t] * rsqrtf(var + EPSV);
    sm[t] = s; tm[t] = bb[t] - m*s;
    __syncthreads();
    if (t < 64){
        float b = bm2[t];
        for (int k = 0; k < 128; ++k){
            float w = Wm2[k*64 + t];
            b += tm[k]*w;
            gb[OFF_W2F + k*64 + t] = sm[k]*w;
        }
        gb[OFF_B2F + t] = b;
    }
}

// ---------------- launch ----------------
extern "C" void kernel_launch(void* const* d_in, const int* in_sizes, int n_in,
                              void* d_out, int out_size){
    (void)in_sizes; (void)n_in; (void)out_size;
    const float* x    = (const float*)d_in[0];
    const int*   ei   = (const int*)  d_in[1];
    const float* ea   = (const float*)d_in[2];
    const int*   esrc = (const int*)  d_in[3];
    const int*   etgt = (const int*)  d_in[4];
    const float* W1l  = (const float*)d_in[5];
    const float* b1   = (const float*)d_in[6];
    const float* W1r  = (const float*)d_in[7];
    const float* W2l  = (const float*)d_in[8];
    const float* b2   = (const float*)d_in[9];
    const float* W2r  = (const float*)d_in[10];
    const float* bn1g = (const float*)d_in[11];
    const float* bn1b = (const float*)d_in[12];
    const float* bn2g = (const float*)d_in[13];
    const float* bn2b = (const float*)d_in[14];
    const float* We   = (const float*)d_in[15];
    const float* be   = (const float*)d_in[16];
    const float* bneg = (const float*)d_in[17];
    const float* bneb = (const float*)d_in[18];
    const float* Wm1  = (const float*)d_in[19];
    const float* bm1  = (const float*)d_in[20];
    const float* bnmg = (const float*)d_in[21];
    const float* bnmb = (const float*)d_in[22];
    const float* Wm2  = (const float*)d_in[23];
    const float* bm2  = (const float*)d_in[24];
    const float* Wm3  = (const float*)d_in[25];
    const float* bm3  = (const float*)d_in[26];
    float* out = (float*)d_out;

    float* gb = nullptr;
    cudaGetSymbolAddress((void**)&gb, g_buf);
    int* ib = nullptr;
    cudaGetSymbolAddress((void**)&ib, g_ibuf);

    const int* src = ei;
    const int* dst = ei + NE;

    int* csr_cnt = ib + IOFF_CNT;
    int* csr_off = ib + IOFF_OFF;
    int* csr_cur = ib + IOFF_CUR;
    int* csr_bs  = ib + IOFF_BSUM;
    int* csr_el  = ib + IOFF_EL;

    float* st   = gb + OFF_STAT;
    float* bn1s = st + 0,   *bn1q = st + 128;
    float* bn2s = st + 256, *bn2q = st + 384;
    float* bnes = st + 512, *bneq = st + 640;
    float* bnms = st + 768, *bnmq = st + 896;

    // zero stats + CSR counters
    cudaMemsetAsync(gb, 0, 1024 * sizeof(float), 0);
    cudaMemsetAsync(csr_cnt, 0, NP * sizeof(int), 0);

    k_copy_x<<<(NP*32 + 255)/256, 256>>>(x, gb + OFF_XP);
    k_prep_weights<<<(64*128 + 256*128 + 128*256 + 255)/256, 256>>>(W1l, W1r, W2l, W2r, Wm1, gb);

    // ---- CSR build (shared by both SAGE layers) ----
    k_hist<<<(NE + 255)/256, 256>>>(dst, csr_cnt);
    k_blocksum<<<NB_SCAN, 256>>>(csr_cnt, csr_bs);
    k_scanb<<<1, 64>>>(csr_bs);
    k_offsets<<<NB_SCAN, 256>>>(csr_cnt, csr_bs, csr_off, csr_cur);
    k_fill<<<(NE + 255)/256, 256>>>(src, dst, csr_cur, csr_el);

    // ---- layer 1 ----
    k_agg1<<<(NP*32 + 255)/256, 256>>>(x, csr_off, csr_cnt, csr_el, gb + OFF_M1);
    gemm_k<64,128,8,8,1,true><<<dim3(NP/64,1), 128>>>(
        gb+OFF_M1, gb+OFF_XP, gb+OFF_WC1, 128, b1, gb+OFF_H1, 128, NND,
        bn1s, bn1q, nullptr, nullptr, nullptr);
    k_bnapply<<<(NND*128 + 255)/256, 256>>>(gb+OFF_H1, NND, bn1s, bn1q, bn1g, bn1b);

    // ---- layer 2 ----
    k_agg2<<<(NP*32 + 255)/256, 256>>>(gb+OFF_H1, csr_off, csr_cnt, csr_el, gb + OFF_M2);
    gemm_k<256,128,8,8,1,true><<<dim3(NP/64,1), 128>>>(
        gb+OFF_M2, gb+OFF_H1, gb+OFF_WC2, 128, b2, gb+OFF_H2, 128, NND,
        bn2s, bn2q, nullptr, nullptr, nullptr);
    k_bnapply<<<(NND*128 + 255)/256, 256>>>(gb+OFF_H2, NND, bn2s, bn2q, bn2g, bn2b);

    // ---- node transforms u|v = h2 @ [Wm1_A | Wm1_B] ----
    gemm_k<128,128,8,8,0,false><<<dim3(NP/64,2), 128>>>(
        gb+OFF_H2, nullptr, gb+OFF_BUV, 256, nullptr, gb+OFF_UV, 256, NP,
        nullptr, nullptr, nullptr, nullptr, nullptr);

    // ---- edge encoder: RE = relu(ea @ We + be), stats for bne ----
    gemm_k<16,128,8,8,2,false><<<dim3(NE/64,1), 128>>>(
        ea, nullptr, We, 128, be, gb+OFF_RE, 128, NE,
        bnes, bneq, nullptr, nullptr, nullptr);
    k_prep_ef<<<1,128>>>(Wm1, bm1, bneg, bneb, gb);

    // ---- z1 via legacy tensor-core mma (tf32); stats via separate pass ----
    z1_mma<<<NE/128, 256>>>(gb+OFF_RE, gb+OFF_BFRAG, gb+OFF_BM1F,
                            esrc, etgt, gb+OFF_UV, gb+OFF_Z1);
    k_colstats<<<NE/256, 256>>>(gb+OFF_Z1, bnms, bnmq);
    k_prep_m<<<1,128>>>(Wm2, bm2, bnmg, bnmb, gb);

    // ---- out = relu(z1 @ Wm2' + b2') @ Wm3 + bm3 ----
    gemm_k<128,64,8,4,4,false><<<dim3(NE/64,1), 128>>>(
        gb+OFF_Z1, nullptr, gb+OFF_W2F, 64, gb+OFF_B2F, nullptr, 0, NE,
        nullptr, nullptr, Wm3, bm3, out);
}

// round 16
// speedup vs baseline: 1.4783x; 1.0929x over previous
#include <cuda_runtime.h>
#include <cstdint>
#include <cstddef>

#define EPSV 1e-5f
constexpr int NND = 100000;   // nodes
constexpr int NE  = 800000;   // edges
constexpr int NP  = 100032;   // nodes padded to multiple of 64
constexpr int NB_SCAN = (NP + 2047) / 2048;   // 49 scan blocks

// ---------------- float scratch ----------------
constexpr size_t OFF_STAT = 0;                                // 1024 (zeroed)
constexpr size_t OFF_XP   = 1024;                             // NP*32
constexpr size_t OFF_M1   = OFF_XP  + (size_t)NP*32;          // NP*32
constexpr size_t OFF_H1   = OFF_M1  + (size_t)NP*32;          // NP*128
constexpr size_t OFF_M2   = OFF_H1  + (size_t)NP*128;         // NP*128
constexpr size_t OFF_H2   = OFF_M2  + (size_t)NP*128;         // NP*128
constexpr size_t OFF_UV   = OFF_H2  + (size_t)NP*128;         // NP*256
constexpr size_t OFF_RE   = OFF_UV  + (size_t)NP*256;         // NE*128
constexpr size_t OFF_Z1   = OFF_RE  + (size_t)NE*128;         // NE*128
constexpr size_t OFF_WC1  = OFF_Z1  + (size_t)NE*128;         // 64*128
constexpr size_t OFF_WC2  = OFF_WC1 + 64*128;                 // 256*128
constexpr size_t OFF_BUV  = OFF_WC2 + 256*128;                // 128*256
constexpr size_t OFF_BFRAG= OFF_BUV + 128*256;                // 16384 (tf32 B fragments, z1)
constexpr size_t OFF_BM1F = OFF_BFRAG + 128*128;              // 128
constexpr size_t OFF_W2FRAG = OFF_BM1F + 128;                 // 8192 (tf32 B fragments, out)
constexpr size_t OFF_B2F  = OFF_W2FRAG + 128*64;              // 64
constexpr size_t GBUF_TOTAL = OFF_B2F + 64;

__device__ float g_buf[GBUF_TOTAL];

// ---------------- int scratch (CSR) ----------------
constexpr size_t IOFF_CNT  = 0;                 // NP (zeroed)
constexpr size_t IOFF_OFF  = IOFF_CNT + NP;     // NP
constexpr size_t IOFF_CUR  = IOFF_OFF + NP;     // NP
constexpr size_t IOFF_BSUM = IOFF_CUR + NP;     // 64
constexpr size_t IOFF_EL   = IOFF_BSUM + 64;    // NE
constexpr size_t IBUF_TOTAL = IOFF_EL + NE;

__device__ int g_ibuf[IBUF_TOTAL];

// ---------------- tf32 helpers ----------------
__device__ __forceinline__ uint32_t tf32u(float x){
    uint32_t u;
    asm("cvt.rna.tf32.f32 %0, %1;" : "=r"(u) : "f"(x));
    return u;
}
__device__ __forceinline__ float to_tf32f(float x){
    return __uint_as_float(tf32u(x));
}

// legacy tensor-core mma (HMMA path; supported on base sm_103 target)
__device__ __forceinline__ void mma16n8k8(float* d, const uint32_t* a, const uint32_t* b){
    asm volatile(
        "mma.sync.aligned.m16n8k8.row.col.f32.tf32.tf32.f32 "
        "{%0,%1,%2,%3}, {%4,%5,%6,%7}, {%8,%9}, {%0,%1,%2,%3};"
        : "+f"(d[0]), "+f"(d[1]), "+f"(d[2]), "+f"(d[3])
        : "r"(a[0]), "r"(a[1]), "r"(a[2]), "r"(a[3]), "r"(b[0]), "r"(b[1]));
}

// ---------------- CSR build ----------------
__global__ void k_hist(const int* __restrict__ dst, int* __restrict__ cnt){
    int e = blockIdx.x*256 + threadIdx.x;
    if (e < NE) atomicAdd(&cnt[dst[e]], 1);
}

__global__ void k_blocksum(const int* __restrict__ cnt, int* __restrict__ bsum){
    __shared__ int sh[256];
    int base = blockIdx.x*2048 + threadIdx.x*8;
    int s = 0;
#pragma unroll
    for (int j=0;j<8;j++){ int i = base + j; if (i < NP) s += cnt[i]; }
    sh[threadIdx.x] = s; __syncthreads();
    for (int o=128;o>0;o>>=1){ if (threadIdx.x<o) sh[threadIdx.x]+=sh[threadIdx.x+o]; __syncthreads(); }
    if (threadIdx.x==0) bsum[blockIdx.x] = sh[0];
}

__global__ void k_scanb(int* __restrict__ bsum){
    __shared__ int sh[64];
    int t = threadIdx.x;
    int v = (t < NB_SCAN) ? bsum[t] : 0;
    sh[t] = v; __syncthreads();
    for (int o=1;o<64;o<<=1){
        int tmp = (t>=o) ? sh[t-o] : 0;
        __syncthreads();
        sh[t] += tmp;
        __syncthreads();
    }
    if (t < NB_SCAN) bsum[t] = sh[t] - v;   // exclusive
}

__global__ void k_offsets(const int* __restrict__ cnt, const int* __restrict__ bsum,
                          int* __restrict__ off, int* __restrict__ cur){
    __shared__ int sh[256];
    int base = blockIdx.x*2048 + threadIdx.x*8;
    int loc[8]; int s = 0;
#pragma unroll
    for (int j=0;j<8;j++){ int i = base + j; int c = (i<NP)?cnt[i]:0; loc[j]=s; s+=c; }
    sh[threadIdx.x] = s; __syncthreads();
    int v = s;
    for (int o=1;o<256;o<<=1){
        int tmp = (threadIdx.x>=o) ? sh[threadIdx.x-o] : 0;
        __syncthreads();
        sh[threadIdx.x] += tmp;
        __syncthreads();
    }
    int ex = sh[threadIdx.x] - v + bsum[blockIdx.x];
#pragma unroll
    for (int j=0;j<8;j++){
        int i = base + j;
        if (i < NP){ int o_ = ex + loc[j]; off[i]=o_; cur[i]=o_; }
    }
}

__global__ void k_fill(const int* __restrict__ src, const int* __restrict__ dst,
                       int* __restrict__ cur, int* __restrict__ elist){
    int e = blockIdx.x*256 + threadIdx.x;
    if (e >= NE) return;
    int p = atomicAdd(&cur[dst[e]], 1);
    elist[p] = src[e];
}

// ---------------- gather-based mean aggregation ----------------
__global__ void k_agg1(const float* __restrict__ x, const int* __restrict__ off,
                       const int* __restrict__ cnt, const int* __restrict__ elist,
                       float* __restrict__ m1){
    int w = (blockIdx.x*256 + threadIdx.x) >> 5;
    int lane = threadIdx.x & 31;
    if (w >= NP) return;
    int o = off[w], d = cnt[w];
    float s = 0.f;
    for (int j=0;j<d;j++){
        int sn = __ldg(&elist[o+j]);
        s += __ldg(&x[(size_t)sn*32 + lane]);
    }
    m1[(size_t)w*32 + lane] = s / fmaxf((float)d, 1.f);
}

__global__ void k_agg2(const float* __restrict__ h1, const int* __restrict__ off,
                       const int* __restrict__ cnt, const int* __restrict__ elist,
                       float* __restrict__ m2){
    int w = (blockIdx.x*256 + threadIdx.x) >> 5;
    int lane = threadIdx.x & 31;
    if (w >= NP) return;
    int o = off[w], d = cnt[w];
    float4 s = make_float4(0.f,0.f,0.f,0.f);
    for (int j=0;j<d;j++){
        int sn = __ldg(&elist[o+j]);
        float4 v = *reinterpret_cast<const float4*>(h1 + (size_t)sn*128 + lane*4);
        s.x += v.x; s.y += v.y; s.z += v.z; s.w += v.w;
    }
    float inv = 1.f / fmaxf((float)d, 1.f);
    s.x *= inv; s.y *= inv; s.z *= inv; s.w *= inv;
    *reinterpret_cast<float4*>(m2 + (size_t)w*128 + lane*4) = s;
}

// ---------------- generic register-blocked GEMM with fused epilogues ----------------
// EPI 0: +bias, store
// EPI 1: +bias, store, column stats (rows < Mreal)
// EPI 2: +bias, relu, store, stats
template<int K, int BN, int TM, int TN, int EPI, bool SPLITA>
__global__ void __launch_bounds__(128)
gemm_k(const float* __restrict__ A0, const float* __restrict__ A1,
       const float* __restrict__ B, int ldb,
       const float* __restrict__ bias,
       float* __restrict__ C, int ldc, int Mreal,
       float* __restrict__ gsum, float* __restrict__ gsq)
{
    constexpr int BM = 64, BK = 16;
    constexpr int TCOLS = BN / TN;
    constexpr int LDA = SPLITA ? (K/2) : K;

    __shared__ float As[BK][BM + 4];
    __shared__ float Bs[BK][BN];
    __shared__ float s_sum[(EPI>=1 && EPI<=2) ? BN : 1];
    __shared__ float s_sq [(EPI>=1 && EPI<=2) ? BN : 1];

    const int tid = threadIdx.x;
    const int row0 = blockIdx.x * BM;
    const int colblk = blockIdx.y * BN;

    float acc[TM][TN];
#pragma unroll
    for (int i=0;i<TM;i++)
#pragma unroll
        for (int j=0;j<TN;j++) acc[i][j]=0.f;

    const int tc = tid % TCOLS, tr = tid / TCOLS;

    for (int k0 = 0; k0 < K; k0 += BK) {
#pragma unroll
        for (int p = 0; p < 2; ++p) {
            int ar = (tid >> 2) + p*32;
            int ac = (tid & 3) * 4;
            int grow = row0 + ar;
            int gk = k0 + ac;
            const float* Ap = A0; int kk = gk;
            if (SPLITA && gk >= K/2) { Ap = A1; kk = gk - K/2; }
            float4 v = *reinterpret_cast<const float4*>(Ap + (size_t)grow*LDA + kk);
            As[ac+0][ar]=v.x; As[ac+1][ar]=v.y; As[ac+2][ar]=v.z; As[ac+3][ar]=v.w;
        }
        constexpr int BLD = (BK*BN)/(128*4);
#pragma unroll
        for (int p = 0; p < BLD; ++p) {
            int lin = tid + p*128;
            int br = lin / (BN/4);
            int bc = (lin % (BN/4)) * 4;
            float4 v = *reinterpret_cast<const float4*>(B + (size_t)(k0+br)*ldb + colblk + bc);
            *reinterpret_cast<float4*>(&Bs[br][bc]) = v;
        }
        __syncthreads();
#pragma unroll
        for (int kk = 0; kk < BK; ++kk) {
            float a[TM], b[TN];
#pragma unroll
            for (int i=0;i<TM;i++) a[i] = As[kk][tr*TM+i];
#pragma unroll
            for (int j=0;j<TN;j++) b[j] = Bs[kk][tc*TN+j];
#pragma unroll
            for (int i=0;i<TM;i++)
#pragma unroll
                for (int j=0;j<TN;j++) acc[i][j] = fmaf(a[i], b[j], acc[i][j]);
        }
        __syncthreads();
    }

    const int gc0 = colblk + tc*TN;
    float breg[TN];
#pragma unroll
    for (int j=0;j<TN;j++) breg[j] = bias ? bias[gc0+j] : 0.f;

    float cs[TN], cq[TN];
#pragma unroll
    for (int j=0;j<TN;j++){ cs[j]=0.f; cq[j]=0.f; }

    if constexpr (EPI == 0 || EPI == 1) {
#pragma unroll
        for (int i=0;i<TM;i++){
            int r = row0 + tr*TM + i;
#pragma unroll
            for (int j=0;j<TN;j++){
                float v = acc[i][j] + breg[j];
                C[(size_t)r*ldc + gc0 + j] = v;
                if (EPI==1 && r < Mreal){ cs[j]+=v; cq[j]+=v*v; }
            }
        }
    } else if constexpr (EPI == 2) {
#pragma unroll
        for (int i=0;i<TM;i++){
            int r = row0 + tr*TM + i;
#pragma unroll
            for (int j=0;j<TN;j++){
                float v = fmaxf(acc[i][j] + breg[j], 0.f);
                C[(size_t)r*ldc + gc0 + j] = v;
                if (r < Mreal){ cs[j]+=v; cq[j]+=v*v; }
            }
        }
    }

    if constexpr (EPI >= 1 && EPI <= 2) {
        for (int i=tid;i<BN;i+=128){ s_sum[i]=0.f; s_sq[i]=0.f; }
        __syncthreads();
#pragma unroll
        for (int j=0;j<TN;j++){
            atomicAdd(&s_sum[tc*TN+j], cs[j]);
            atomicAdd(&s_sq [tc*TN+j], cq[j]);
        }
        __syncthreads();
        for (int i=tid;i<BN;i+=128){
            atomicAdd(&gsum[colblk+i], s_sum[i]);
            atomicAdd(&gsq [colblk+i], s_sq[i]);
        }
    }
}

// ---------------- z1 via legacy tensor-core mma (tf32) ----------------
constexpr int Z_LDA = 68;   // smem row stride (floats): conflict-free frags

__global__ void __launch_bounds__(256)
z1_mma(const float* __restrict__ RE, const float* __restrict__ Bf,
       const float* __restrict__ bias, const int* __restrict__ es, const int* __restrict__ et,
       const float* __restrict__ uv, float* __restrict__ z1)
{
    __shared__ float As[128 * Z_LDA + 4];
    const int tid = threadIdx.x;
    const int w = tid >> 5;
    const int lane = tid & 31;
    const int g = lane >> 2;        // groupID
    const int t = lane & 3;         // threadID_in_group
    const int wm = w >> 1;          // 0..3   (32-row strip)
    const int wn = w & 1;           // 0..1   (64-col strip)
    const int R  = wm * 32;
    const int Cn = wn * 64;
    const int row0 = blockIdx.x * 128;

    float acc[2][8][4];
#pragma unroll
    for (int i=0;i<2;i++)
#pragma unroll
        for (int j=0;j<8;j++)
#pragma unroll
            for (int q=0;q<4;q++) acc[i][j][q]=0.f;

    for (int c = 0; c < 2; ++c) {
#pragma unroll
        for (int p = 0; p < 8; ++p) {
            int fid = tid + p*256;          // 0..2047 float4s
            int row = fid >> 4;
            int c4  = (fid & 15) * 4;
            float4 v = *reinterpret_cast<const float4*>(RE + (size_t)(row0+row)*128 + c*64 + c4);
            float* dstp = &As[row*Z_LDA + c4];
            dstp[0] = __uint_as_float(tf32u(v.x));
            dstp[1] = __uint_as_float(tf32u(v.y));
            dstp[2] = __uint_as_float(tf32u(v.z));
            dstp[3] = __uint_as_float(tf32u(v.w));
        }
        __syncthreads();

#pragma unroll
        for (int ks = 0; ks < 8; ++ks) {
            int kb = ks * 8;
            uint32_t a[2][4];
#pragma unroll
            for (int mt = 0; mt < 2; ++mt) {
                int rb = R + mt*16 + g;
                a[mt][0] = __float_as_uint(As[(rb    )*Z_LDA + kb + t    ]);
                a[mt][1] = __float_as_uint(As[(rb + 8)*Z_LDA + kb + t    ]);
                a[mt][2] = __float_as_uint(As[(rb    )*Z_LDA + kb + t + 4]);
                a[mt][3] = __float_as_uint(As[(rb + 8)*Z_LDA + kb + t + 4]);
            }
            int ksg = c*8 + ks;
#pragma unroll
            for (int nt = 0; nt < 8; ++nt) {
                int gnt = wn*8 + nt;
                float2 bb = *reinterpret_cast<const float2*>(Bf + ((size_t)(ksg*16 + gnt)*32 + lane)*2);
                uint32_t b[2] = { __float_as_uint(bb.x), __float_as_uint(bb.y) };
                mma16n8k8(acc[0][nt], a[0], b);
                mma16n8k8(acc[1][nt], a[1], b);
            }
        }
        __syncthreads();
    }

#pragma unroll
    for (int mt = 0; mt < 2; ++mt) {
        int r_lo = row0 + R + mt*16 + g;
        int r_hi = r_lo + 8;
        int e1a = es[r_lo], e2a = et[r_lo];
        int e1b = es[r_hi], e2b = et[r_hi];
        const float* ua = uv + (size_t)e1a*256;
        const float* va = uv + (size_t)e2a*256 + 128;
        const float* ub = uv + (size_t)e1b*256;
        const float* vb = uv + (size_t)e2b*256 + 128;
#pragma unroll
        for (int nt = 0; nt < 8; ++nt) {
            int col = Cn + nt*8 + 2*t;
            float2 bi = *reinterpret_cast<const float2*>(bias + col);
            float2 u1 = *reinterpret_cast<const float2*>(ua + col);
            float2 v1 = *reinterpret_cast<const float2*>(va + col);
            float2 u2 = *reinterpret_cast<const float2*>(ub + col);
            float2 v2 = *reinterpret_cast<const float2*>(vb + col);
            float2 olo, ohi;
            olo.x = fmaxf(acc[mt][nt][0] + bi.x + u1.x + v1.x, 0.f);
            olo.y = fmaxf(acc[mt][nt][1] + bi.y + u1.y + v1.y, 0.f);
            ohi.x = fmaxf(acc[mt][nt][2] + bi.x + u2.x + v2.x, 0.f);
            ohi.y = fmaxf(acc[mt][nt][3] + bi.y + u2.y + v2.y, 0.f);
            *reinterpret_cast<float2*>(z1 + (size_t)r_lo*128 + col) = olo;
            *reinterpret_cast<float2*>(z1 + (size_t)r_hi*128 + col) = ohi;
        }
    }
}

// ---------------- out GEMM via legacy tensor-core mma (tf32) ----------------
// out[r] = sum_n relu( sum_k z1[r,k]*W2f[k][n] + b2f[n] ) * wm3[n] + bm3
__global__ void __launch_bounds__(256)
out_mma(const float* __restrict__ z1, const float* __restrict__ Bf,
        const float* __restrict__ b2f, const float* __restrict__ wm3,
        const float* __restrict__ bm3, float* __restrict__ out)
{
    __shared__ float As[128 * Z_LDA + 4];
    const int tid = threadIdx.x;
    const int w = tid >> 5;
    const int lane = tid & 31;
    const int g = lane >> 2;
    const int t = lane & 3;
    const int row0 = blockIdx.x * 128;

    float acc[8][4];
#pragma unroll
    for (int j=0;j<8;j++)
#pragma unroll
        for (int q=0;q<4;q++) acc[j][q]=0.f;

    for (int c = 0; c < 2; ++c) {
#pragma unroll
        for (int p = 0; p < 8; ++p) {
            int fid = tid + p*256;
            int row = fid >> 4;
            int c4  = (fid & 15) * 4;
            float4 v = *reinterpret_cast<const float4*>(z1 + (size_t)(row0+row)*128 + c*64 + c4);
            float* dstp = &As[row*Z_LDA + c4];
            dstp[0] = __uint_as_float(tf32u(v.x));
            dstp[1] = __uint_as_float(tf32u(v.y));
            dstp[2] = __uint_as_float(tf32u(v.z));
            dstp[3] = __uint_as_float(tf32u(v.w));
        }
        __syncthreads();

#pragma unroll
        for (int ks = 0; ks < 8; ++ks) {
            int kb = ks * 8;
            int rb = w*16 + g;
            uint32_t a[4];
            a[0] = __float_as_uint(As[(rb    )*Z_LDA + kb + t    ]);
            a[1] = __float_as_uint(As[(rb + 8)*Z_LDA + kb + t    ]);
            a[2] = __float_as_uint(As[(rb    )*Z_LDA + kb + t + 4]);
            a[3] = __float_as_uint(As[(rb + 8)*Z_LDA + kb + t + 4]);
            int ksg = c*8 + ks;
#pragma unroll
            for (int nt = 0; nt < 8; ++nt) {
                float2 bb = *reinterpret_cast<const float2*>(Bf + ((size_t)(ksg*8 + nt)*32 + lane)*2);
                uint32_t b[2] = { __float_as_uint(bb.x), __float_as_uint(bb.y) };
                mma16n8k8(acc[nt], a, b);
            }
        }
        __syncthreads();
    }

    // epilogue: relu + dot with wm3, quad reduce over t
    int r_lo = row0 + w*16 + g;
    int r_hi = r_lo + 8;
    float plo = 0.f, phi = 0.f;
#pragma unroll
    for (int nt = 0; nt < 8; ++nt) {
        int col = nt*8 + 2*t;
        float2 bi = *reinterpret_cast<const float2*>(b2f + col);
        float2 w3 = *reinterpret_cast<const float2*>(wm3 + col);
        plo += fmaxf(acc[nt][0] + bi.x, 0.f)*w3.x + fmaxf(acc[nt][1] + bi.y, 0.f)*w3.y;
        phi += fmaxf(acc[nt][2] + bi.x, 0.f)*w3.x + fmaxf(acc[nt][3] + bi.y, 0.f)*w3.y;
    }
    plo += __shfl_xor_sync(0xffffffffu, plo, 1);
    plo += __shfl_xor_sync(0xffffffffu, plo, 2);
    phi += __shfl_xor_sync(0xffffffffu, phi, 1);
    phi += __shfl_xor_sync(0xffffffffu, phi, 2);
    if (t == 0) {
        float b = bm3[0];
        out[r_lo] = plo + b;
        out[r_hi] = phi + b;
    }
}

// ---------------- column stats over z1 (for bnm fold) ----------------
__global__ void k_colstats(const float* __restrict__ z1,
                           float* __restrict__ gsum, float* __restrict__ gsq){
    __shared__ float ss[256], sq[256];
    int col = threadIdx.x & 127;
    int half = threadIdx.x >> 7;     // 0 or 1
    size_t rbase = (size_t)blockIdx.x * 256 + half;
    float s = 0.f, q = 0.f;
#pragma unroll 4
    for (int i = 0; i < 128; ++i) {
        float v = __ldg(&z1[(rbase + (size_t)i*2) * 128 + col]);
        s += v; q += v*v;
    }
    ss[threadIdx.x] = s; sq[threadIdx.x] = q;
    __syncthreads();
    if (threadIdx.x < 128) {
        atomicAdd(&gsum[col], ss[threadIdx.x] + ss[threadIdx.x + 128]);
        atomicAdd(&gsq [col], sq[threadIdx.x] + sq[threadIdx.x + 128]);
    }
}

// ---------------- elementwise / prep kernels ----------------
__global__ void k_copy_x(const float* __restrict__ x, float* __restrict__ xp){
    int i = blockIdx.x*256 + threadIdx.x;
    if (i < NP*32) xp[i] = (i < NND*32) ? x[i] : 0.f;
}

__global__ void k_prep_weights(const float* __restrict__ W1l, const float* __restrict__ W1r,
                               const float* __restrict__ W2l, const float* __restrict__ W2r,
                               const float* __restrict__ Wm1, float* __restrict__ gb){
    int i = blockIdx.x*256 + threadIdx.x;
    if (i < 64*128){
        int r = i>>7, c = i&127;
        gb[OFF_WC1 + i] = (r<32) ? W1l[r*128+c] : W1r[(r-32)*128+c];
    } else if (i < 64*128 + 256*128){
        int j = i - 64*128; int r = j>>7, c = j&127;
        gb[OFF_WC2 + j] = (r<128) ? W2l[r*128+c] : W2r[(r-128)*128+c];
    } else if (i < 64*128 + 256*128 + 128*256){
        int j = i - 64*128 - 256*128; int k = j>>8, c = j&255;
        gb[OFF_BUV + j] = (c<128) ? Wm1[k*128+c] : Wm1[(128+k)*128 + (c-128)];
    }
}

__global__ void k_bnapply(float* __restrict__ buf, int n,
                          const float* __restrict__ ss, const float* __restrict__ sq,
                          const float* __restrict__ g, const float* __restrict__ b){
    int i = blockIdx.x*256 + threadIdx.x;
    if (i >= n*128) return;
    int c = i & 127;
    float m = ss[c] / (float)n;
    float var = sq[c] / (float)n - m*m;
    float s = g[c] * rsqrtf(var + EPSV);
    float v = buf[i]*s + (b[c] - m*s);
    buf[i] = fmaxf(v, 0.f);
}

// fold ef-BN into Wm1_C; emit bias and B in mma fragment-major tf32 layout
__global__ void k_prep_ef(const float* __restrict__ Wm1, const float* __restrict__ bm1,
                          const float* __restrict__ bg, const float* __restrict__ bb,
                          float* __restrict__ gb){
    __shared__ float se[128], te[128];
    int t = threadIdx.x;   // output column n
    float m = gb[OFF_STAT + 512 + t] / (float)NE;
    float var = gb[OFF_STAT + 640 + t] / (float)NE - m*m;
    float s = bg[t] * rsqrtf(var + EPSV);
    se[t] = s; te[t] = bb[t] - m*s;
    __syncthreads();
    float bacc = bm1[t];
    for (int k = 0; k < 128; ++k){
        bacc += te[k] * Wm1[(size_t)(256+k)*128 + t];
    }
    gb[OFF_BM1F + t] = bacc;
    // B fragments: lin = ((ks*16 + nt)*32 + lane)*2 + r
    for (int j = 0; j < 128; ++j){
        int lin = t*128 + j;
        int r    = lin & 1;
        int lane = (lin >> 1) & 31;
        int nt   = (lin >> 6) & 15;
        int ks   = lin >> 10;
        int n = nt*8 + (lane >> 2);
        int k = ks*8 + (lane & 3) + 4*r;
        gb[OFF_BFRAG + lin] = to_tf32f(se[k] * Wm1[(size_t)(256+k)*128 + n]);
    }
}

// fold bnm (stats over z1) into Wm2: emit fragment-major tf32 + folded bias
__global__ void k_prep_m(const float* __restrict__ Wm2, const float* __restrict__ bm2,
                         const float* __restrict__ bg, const float* __restrict__ bb,
                         float* __restrict__ gb){
    __shared__ float sm[128], tm[128];
    int t = threadIdx.x;
    float m = gb[OFF_STAT + 768 + t] / (float)NE;
    float var = gb[OFF_STAT + 896 + t] / (float)NE - m*m;
    float s = bg[t] * rsqrtf(var + EPSV);
    sm[t] = s; tm[t] = bb[t] - m*s;
    __syncthreads();
    if (t < 64){
        float b = bm2[t];
        for (int k = 0; k < 128; ++k){
            b += tm[k] * Wm2[k*64 + t];
        }
        gb[OFF_B2F + t] = b;
    }
    // W2 fragments: lin = ((ks*8 + nt)*32 + lane)*2 + r  (8192 total, 64 per thread)
    for (int j = 0; j < 64; ++j){
        int lin = t*64 + j;
        int r    = lin & 1;
        int lane = (lin >> 1) & 31;
        int nt   = (lin >> 6) & 7;
        int ks   = lin >> 9;
        int n = nt*8 + (lane >> 2);
        int k = ks*8 + (lane & 3) + 4*r;
        gb[OFF_W2FRAG + lin] = to_tf32f(sm[k] * Wm2[(size_t)k*64 + n]);
    }
}

// ---------------- launch ----------------
extern "C" void kernel_launch(void* const* d_in, const int* in_sizes, int n_in,
                              void* d_out, int out_size){
    (void)in_sizes; (void)n_in; (void)out_size;
    const float* x    = (const float*)d_in[0];
    const int*   ei   = (const int*)  d_in[1];
    const float* ea   = (const float*)d_in[2];
    const int*   esrc = (const int*)  d_in[3];
    const int*   etgt = (const int*)  d_in[4];
    const float* W1l  = (const float*)d_in[5];
    const float* b1   = (const float*)d_in[6];
    const float* W1r  = (const float*)d_in[7];
    const float* W2l  = (const float*)d_in[8];
    const float* b2   = (const float*)d_in[9];
    const float* W2r  = (const float*)d_in[10];
    const float* bn1g = (const float*)d_in[11];
    const float* bn1b = (const float*)d_in[12];
    const float* bn2g = (const float*)d_in[13];
    const float* bn2b = (const float*)d_in[14];
    const float* We   = (const float*)d_in[15];
    const float* be   = (const float*)d_in[16];
    const float* bneg = (const float*)d_in[17];
    const float* bneb = (const float*)d_in[18];
    const float* Wm1  = (const float*)d_in[19];
    const float* bm1  = (const float*)d_in[20];
    const float* bnmg = (const float*)d_in[21];
    const float* bnmb = (const float*)d_in[22];
    const float* Wm2  = (const float*)d_in[23];
    const float* bm2  = (const float*)d_in[24];
    const float* Wm3  = (const float*)d_in[25];
    const float* bm3  = (const float*)d_in[26];
    float* out = (float*)d_out;

    float* gb = nullptr;
    cudaGetSymbolAddress((void**)&gb, g_buf);
    int* ib = nullptr;
    cudaGetSymbolAddress((void**)&ib, g_ibuf);

    const int* src = ei;
    const int* dst = ei + NE;

    int* csr_cnt = ib + IOFF_CNT;
    int* csr_off = ib + IOFF_OFF;
    int* csr_cur = ib + IOFF_CUR;
    int* csr_bs  = ib + IOFF_BSUM;
    int* csr_el  = ib + IOFF_EL;

    float* st   = gb + OFF_STAT;
    float* bn1s = st + 0,   *bn1q = st + 128;
    float* bn2s = st + 256, *bn2q = st + 384;
    float* bnes = st + 512, *bneq = st + 640;
    float* bnms = st + 768, *bnmq = st + 896;

    // zero stats + CSR counters
    cudaMemsetAsync(gb, 0, 1024 * sizeof(float), 0);
    cudaMemsetAsync(csr_cnt, 0, NP * sizeof(int), 0);

    k_copy_x<<<(NP*32 + 255)/256, 256>>>(x, gb + OFF_XP);
    k_prep_weights<<<(64*128 + 256*128 + 128*256 + 255)/256, 256>>>(W1l, W1r, W2l, W2r, Wm1, gb);

    // ---- CSR build (shared by both SAGE layers) ----
    k_hist<<<(NE + 255)/256, 256>>>(dst, csr_cnt);
    k_blocksum<<<NB_SCAN, 256>>>(csr_cnt, csr_bs);
    k_scanb<<<1, 64>>>(csr_bs);
    k_offsets<<<NB_SCAN, 256>>>(csr_cnt, csr_bs, csr_off, csr_cur);
    k_fill<<<(NE + 255)/256, 256>>>(src, dst, csr_cur, csr_el);

    // ---- layer 1 ----
    k_agg1<<<(NP*32 + 255)/256, 256>>>(x, csr_off, csr_cnt, csr_el, gb + OFF_M1);
    gemm_k<64,128,8,8,1,true><<<dim3(NP/64,1), 128>>>(
        gb+OFF_M1, gb+OFF_XP, gb+OFF_WC1, 128, b1, gb+OFF_H1, 128, NND,
        bn1s, bn1q);
    k_bnapply<<<(NND*128 + 255)/256, 256>>>(gb+OFF_H1, NND, bn1s, bn1q, bn1g, bn1b);

    // ---- layer 2 ----
    k_agg2<<<(NP*32 + 255)/256, 256>>>(gb+OFF_H1, csr_off, csr_cnt, csr_el, gb + OFF_M2);
    gemm_k<256,128,8,8,1,true><<<dim3(NP/64,1), 128>>>(
        gb+OFF_M2, gb+OFF_H1, gb+OFF_WC2, 128, b2, gb+OFF_H2, 128, NND,
        bn2s, bn2q);
    k_bnapply<<<(NND*128 + 255)/256, 256>>>(gb+OFF_H2, NND, bn2s, bn2q, bn2g, bn2b);

    // ---- node transforms u|v = h2 @ [Wm1_A | Wm1_B] ----
    gemm_k<128,128,8,8,0,false><<<dim3(NP/64,2), 128>>>(
        gb+OFF_H2, nullptr, gb+OFF_BUV, 256, nullptr, gb+OFF_UV, 256, NP,
        nullptr, nullptr);

    // ---- edge encoder: RE = relu(ea @ We + be), stats for bne ----
    gemm_k<16,128,8,8,2,false><<<dim3(NE/64,1), 128>>>(
        ea, nullptr, We, 128, be, gb+OFF_RE, 128, NE,
        bnes, bneq);
    k_prep_ef<<<1,128>>>(Wm1, bm1, bneg, bneb, gb);

    // ---- z1 via tensor-core mma (tf32); stats via separate pass ----
    z1_mma<<<NE/128, 256>>>(gb+OFF_RE, gb+OFF_BFRAG, gb+OFF_BM1F,
                            esrc, etgt, gb+OFF_UV, gb+OFF_Z1);
    k_colstats<<<NE/256, 256>>>(gb+OFF_Z1, bnms, bnmq);
    k_prep_m<<<1,128>>>(Wm2, bm2, bnmg, bnmb, gb);

    // ---- out = relu(z1 @ Wm2' + b2') @ Wm3 + bm3 via tensor-core mma ----
    out_mma<<<NE/128, 256>>>(gb+OFF_Z1, gb+OFF_W2FRAG, gb+OFF_B2F, Wm3, bm3, out);
}